// round 11
// baseline (speedup 1.0000x reference)
#include <cuda_runtime.h>
#include <cuda_bf16.h>
#include <cuda_fp16.h>
#include <math.h>
#include <stdint.h>

// Problem dims (fixed by the reference)
#define Bc  4
#define Sc  2048
#define Ec  768
#define Dc  768
#define Hc  12
#define DHc 64
#define Fc  3072

#define LDSH 40                      // fp16 per smem row (80 B pitch)
#define STAGE_BYTES (128 * LDSH * 2) // one matrix, one stage = 10240 B
#define GEMM_SMEM (3 * 2 * STAGE_BYTES)

// scores kernel smem: q tile + 2 k buffers, pitch 72 fp16 (144 B)
#define SQ_PITCH 72
#define SQ_TILE_BYTES (128 * SQ_PITCH * 2)            // 18432
#define SCORES_SMEM (3 * SQ_TILE_BYTES)               // 55296

// ---------------- scratch (device globals: allocation-free) ----------------
__device__ float    g_vt[(size_t)Bc*Hc*DHc*Sc];       // [B,H,dh,S] fp32
__device__ __half   g_ph[(size_t)Bc*Hc*Sc*Sc];        // p = exp(masked score) fp16
__device__ __half   g_vh[(size_t)Bc*Hc*DHc*Sc];       // v / colsum, fp16
__device__ float    g_csp[(size_t)Bc*Hc*16*Sc];       // per-mtile column partial sums
__device__ float    g_colsum[(size_t)Bc*Hc*Sc];
__device__ uint32_t g_mb[(size_t)Bc*Sc*(Sc/32)];      // bit-packed mask
__device__ float    g_a [(size_t)Bc*Sc*Dc];
__device__ float    g_b [(size_t)Bc*Sc*Dc];

// fp16 operand buffers
__device__ __half g_xh [(size_t)Bc*Sc*Ec];
__device__ __half g_ah [(size_t)Bc*Sc*Dc];            // post-LN1 fp16
__device__ __half g_hh [(size_t)Bc*Sc*Fc];            // hidden fp16
__device__ __half g_qh [(size_t)Bc*Hc*Sc*DHc];
__device__ __half g_kh [(size_t)Bc*Hc*Sc*DHc];
__device__ __half g_wqh[(size_t)Dc*Ec];
__device__ __half g_wkh[(size_t)Dc*Ec];
__device__ __half g_wvh[(size_t)Dc*Ec];
__device__ __half g_w1h[(size_t)Fc*Dc];
__device__ __half g_w2h[(size_t)Dc*Fc];

// ======================= warp-MMA helpers ===================================
__device__ __forceinline__ uint32_t smem_u32(const void* p) {
    uint32_t a;
    asm("{ .reg .u64 t; cvta.to.shared.u64 t, %1; cvt.u32.u64 %0, t; }" : "=r"(a) : "l"(p));
    return a;
}
__device__ __forceinline__ void ldsm_x4(uint32_t& r0, uint32_t& r1, uint32_t& r2, uint32_t& r3,
                                        uint32_t addr) {
    asm volatile("ldmatrix.sync.aligned.m8n8.x4.shared.b16 {%0,%1,%2,%3}, [%4];"
                 : "=r"(r0), "=r"(r1), "=r"(r2), "=r"(r3) : "r"(addr));
}
__device__ __forceinline__ void mma16816h(float* d, const uint32_t* a, uint32_t b0, uint32_t b1) {
    asm volatile("mma.sync.aligned.m16n8k16.row.col.f32.f16.f16.f32 "
                 "{%0,%1,%2,%3}, {%4,%5,%6,%7}, {%8,%9}, {%0,%1,%2,%3};"
                 : "+f"(d[0]), "+f"(d[1]), "+f"(d[2]), "+f"(d[3])
                 : "r"(a[0]), "r"(a[1]), "r"(a[2]), "r"(a[3]), "r"(b0), "r"(b1));
}
#define CP_ASYNC16(dst, src) \
    asm volatile("cp.async.cg.shared.global [%0], [%1], 16;" :: "r"(dst), "l"(src))
#define CP_COMMIT() asm volatile("cp.async.commit_group;")
#define CP_WAIT1()  asm volatile("cp.async.wait_group 1;")

// ======================= fp16 NT GEMM via mma.sync ==========================
// C[M,N] = A[M,K] @ B[N,K]^T (fp16 operands, fp32 accumulate), batched via z.
// Tile 128x128x32, 3-stage cp.async, 8 warps (2M x 4N), warp tile 64x32.
// EPI: 0 = +bias -> outF[m*N+n]
//      1 = relu(+bias) -> fp16 outH[m*N+n]
//      3 = V scatter  outF[b,h,d,s]  (+bias)
//      5 = q/k scatter: fp16 outH[(b,h,s),64]  (+bias)
template<int EPI>
__global__ void __launch_bounds__(256, 2)
gemm_mma(const __half* __restrict__ A, const __half* __restrict__ Bw,
         int N, int Kp, long strideA, long strideB,
         const float* __restrict__ bias,
         float* __restrict__ outF, __half* __restrict__ outH)
{
    extern __shared__ char dynsm[];

    const int z = blockIdx.z;
    A  += (size_t)z * strideA;
    Bw += (size_t)z * strideB;

    const int tid  = threadIdx.x;
    const int wid  = tid >> 5;
    const int lane = tid & 31;
    const int m0   = blockIdx.y * 128;
    const int n0   = blockIdx.x * 128;
    const int wm   = (wid & 1) * 64;
    const int wn   = (wid >> 1) * 32;

    const uint32_t smBase = smem_u32(dynsm);

    float acc[4][4][4];
    #pragma unroll
    for (int i = 0; i < 4; ++i)
        #pragma unroll
        for (int j = 0; j < 4; ++j)
            #pragma unroll
            for (int p = 0; p < 4; ++p) acc[i][j][p] = 0.f;

    const int nk = Kp / 32;

    auto stage = [&](int s, int kt) {
        const int kc = kt * 32;
        const uint32_t base = smBase + s * (2 * STAGE_BYTES);
        #pragma unroll
        for (int i = 0; i < 2; ++i) {
            const int id = tid + i * 256;
            const int r  = id >> 2;
            const int c  = (id & 3) * 8;
            const uint32_t dA = base + (uint32_t)(r * 80 + c * 2);
            const uint32_t dB = dA + STAGE_BYTES;
            CP_ASYNC16(dA, &A [(size_t)(m0 + r) * Kp + kc + c]);
            CP_ASYNC16(dB, &Bw[(size_t)(n0 + r) * Kp + kc + c]);
        }
    };

    stage(0, 0); CP_COMMIT();
    stage(1, 1); CP_COMMIT();

    const int lrow = lane & 15;
    const int lcol = (lane >> 4) * 8;

    for (int kt = 0; kt < nk; ++kt) {
        CP_WAIT1();
        __syncthreads();

        const uint32_t aBase = smBase + (kt % 3) * (2 * STAGE_BYTES);
        const uint32_t bBase = aBase + STAGE_BYTES;

        #pragma unroll
        for (int ks = 0; ks < 32; ks += 16) {
            uint32_t a[4][4];
            #pragma unroll
            for (int mi = 0; mi < 4; ++mi) {
                const uint32_t ad = aBase + (uint32_t)(wm + mi * 16 + lrow) * 80
                                          + (uint32_t)(ks + lcol) * 2;
                ldsm_x4(a[mi][0], a[mi][1], a[mi][2], a[mi][3], ad);
            }
            uint32_t b[2][4];
            #pragma unroll
            for (int bj = 0; bj < 2; ++bj) {
                const uint32_t bd = bBase + (uint32_t)(wn + bj * 16 + lrow) * 80
                                          + (uint32_t)(ks + lcol) * 2;
                ldsm_x4(b[bj][0], b[bj][1], b[bj][2], b[bj][3], bd);
            }
            #pragma unroll
            for (int mi = 0; mi < 4; ++mi)
                #pragma unroll
                for (int nj = 0; nj < 4; ++nj)
                    mma16816h(acc[mi][nj], a[mi], b[nj >> 1][nj & 1], b[nj >> 1][(nj & 1) + 2]);
        }

        if (kt + 2 < nk) stage((kt + 2) % 3, kt + 2);
        CP_COMMIT();
    }

    // ---------------- epilogue ----------------
    const int r4 = lane >> 2;
    const int c2 = (lane & 3) * 2;

    #pragma unroll
    for (int mi = 0; mi < 4; ++mi) {
        #pragma unroll
        for (int half = 0; half < 2; ++half) {
            const int m = m0 + wm + mi * 16 + r4 + half * 8;
            #pragma unroll
            for (int nj = 0; nj < 4; ++nj) {
                const int n = n0 + wn + nj * 8 + c2;
                float v0 = acc[mi][nj][half * 2]     + bias[n];
                float v1 = acc[mi][nj][half * 2 + 1] + bias[n + 1];
                if (EPI == 0) {
                    *reinterpret_cast<float2*>(&outF[(size_t)m * N + n]) = make_float2(v0, v1);
                } else if (EPI == 1) {
                    *reinterpret_cast<__half2*>(&outH[(size_t)m * N + n]) =
                        __floats2half2_rn(fmaxf(v0, 0.f), fmaxf(v1, 0.f));
                } else if (EPI == 3) {
                    const int b = m >> 11, s = m & 2047;
                    const int h = n >> 6,  d = n & 63;
                    outF[(((size_t)b * Hc + h) * DHc + d)     * Sc + s] = v0;
                    outF[(((size_t)b * Hc + h) * DHc + d + 1) * Sc + s] = v1;
                } else { // EPI 5: q/k scatter
                    const int b = m >> 11, s = m & 2047;
                    const int h = n >> 6,  d = n & 63;
                    *reinterpret_cast<__half2*>(
                        &outH[(((size_t)b * Hc + h) * Sc + s) * DHc + d]) =
                        __floats2half2_rn(v0, v1);
                }
            }
        }
    }
}

// ======================= scores: q-resident n-loop kernel ===================
// One CTA per (m-tile, z). q tile (128x64) resident in smem; loop over 16
// n-chunks of 128 with double-buffered k. Epilogue per chunk: mask, exp,
// p fp16 store, deterministic column partial sums -> csP[(z,mtile),t].
__global__ void __launch_bounds__(256, 2)
scores_fused(const __half* __restrict__ Q, const __half* __restrict__ K,
             const uint32_t* __restrict__ mb, float scale,
             __half* __restrict__ P, float* __restrict__ csP)
{
    extern __shared__ char dynsm[];
    __shared__ float cs_sm[128];

    const int mtile = blockIdx.x;
    const int z     = blockIdx.y;
    const int m0    = mtile * 128;
    const int bq    = z / Hc;

    const __half* Aq = Q + (size_t)z * Sc * DHc;
    const __half* Bk = K + (size_t)z * Sc * DHc;

    const int tid  = threadIdx.x;
    const int wid  = tid >> 5;
    const int lane = tid & 31;
    const int wm   = (wid & 1) * 64;
    const int wn   = (wid >> 1) * 32;

    const uint32_t qBase = smem_u32(dynsm);
    const uint32_t kBase = qBase + SQ_TILE_BYTES;

    // stage q tile: 128 rows x 64 fp16 (8 x 16B chunks per row)
    #pragma unroll
    for (int i = 0; i < 4; ++i) {
        const int id = tid + i * 256;       // 0..1023
        const int r  = id >> 3;
        const int c  = (id & 7) * 8;
        CP_ASYNC16(qBase + (uint32_t)(r * (SQ_PITCH * 2) + c * 2),
                   &Aq[(size_t)(m0 + r) * DHc + c]);
    }
    CP_COMMIT();

    auto stage_k = [&](int buf, int nc) {
        #pragma unroll
        for (int i = 0; i < 4; ++i) {
            const int id = tid + i * 256;
            const int r  = id >> 3;
            const int c  = (id & 7) * 8;
            CP_ASYNC16(kBase + buf * SQ_TILE_BYTES
                             + (uint32_t)(r * (SQ_PITCH * 2) + c * 2),
                       &Bk[(size_t)(nc * 128 + r) * DHc + c]);
        }
    };

    stage_k(0, 0); CP_COMMIT();
    stage_k(1, 1); CP_COMMIT();

    const int lrow = lane & 15;
    const int lcol = (lane >> 4) * 8;
    const int r4 = lane >> 2;
    const int c2 = (lane & 3) * 2;

    for (int nc = 0; nc < 16; ++nc) {
        CP_WAIT1();
        __syncthreads();

        const uint32_t bB = kBase + (nc & 1) * SQ_TILE_BYTES;

        float acc[4][4][4];
        #pragma unroll
        for (int i = 0; i < 4; ++i)
            #pragma unroll
            for (int j = 0; j < 4; ++j)
                #pragma unroll
                for (int p = 0; p < 4; ++p) acc[i][j][p] = 0.f;

        #pragma unroll
        for (int ks = 0; ks < 64; ks += 16) {
            uint32_t a[4][4];
            #pragma unroll
            for (int mi = 0; mi < 4; ++mi) {
                const uint32_t ad = qBase + (uint32_t)(wm + mi * 16 + lrow) * (SQ_PITCH * 2)
                                          + (uint32_t)(ks + lcol) * 2;
                ldsm_x4(a[mi][0], a[mi][1], a[mi][2], a[mi][3], ad);
            }
            uint32_t b[2][4];
            #pragma unroll
            for (int bj = 0; bj < 2; ++bj) {
                const uint32_t bd = bB + (uint32_t)(wn + bj * 16 + lrow) * (SQ_PITCH * 2)
                                       + (uint32_t)(ks + lcol) * 2;
                ldsm_x4(b[bj][0], b[bj][1], b[bj][2], b[bj][3], bd);
            }
            #pragma unroll
            for (int mi = 0; mi < 4; ++mi)
                #pragma unroll
                for (int nj = 0; nj < 4; ++nj)
                    mma16816h(acc[mi][nj], a[mi], b[nj >> 1][nj & 1], b[nj >> 1][(nj & 1) + 2]);
        }

        // ---- epilogue for this n-chunk ----
        if (tid < 128) cs_sm[tid] = 0.f;
        __syncthreads();

        float cs[4][2];
        #pragma unroll
        for (int nj = 0; nj < 4; ++nj) { cs[nj][0] = 0.f; cs[nj][1] = 0.f; }

        #pragma unroll
        for (int mi = 0; mi < 4; ++mi) {
            #pragma unroll
            for (int half = 0; half < 2; ++half) {
                const int m = m0 + wm + mi * 16 + r4 + half * 8;
                const uint32_t word =
                    mb[((size_t)bq * Sc + m) * (Sc / 32) + (size_t)(nc * 128 + wn) / 32];
                #pragma unroll
                for (int nj = 0; nj < 4; ++nj) {
                    const int n = nc * 128 + wn + nj * 8 + c2;
                    const int bit0 = (word >> (n & 31)) & 1;
                    const int bit1 = (word >> ((n + 1) & 31)) & 1;
                    const float e0 = bit0 ? 0.f : __expf(acc[mi][nj][half * 2]     * scale);
                    const float e1 = bit1 ? 0.f : __expf(acc[mi][nj][half * 2 + 1] * scale);
                    *reinterpret_cast<__half2*>(&P[((size_t)z * Sc + m) * Sc + n]) =
                        __floats2half2_rn(e0, e1);
                    cs[nj][0] += e0; cs[nj][1] += e1;
                }
            }
        }

        #pragma unroll
        for (int nj = 0; nj < 4; ++nj)
            #pragma unroll
            for (int p = 0; p < 2; ++p) {
                float v = cs[nj][p];
                v += __shfl_xor_sync(0xffffffffu, v, 4);
                v += __shfl_xor_sync(0xffffffffu, v, 8);
                v += __shfl_xor_sync(0xffffffffu, v, 16);
                cs[nj][p] = v;
            }
        if (r4 == 0) {
            #pragma unroll
            for (int nj = 0; nj < 4; ++nj) {
                atomicAdd(&cs_sm[wn + nj * 8 + c2],     cs[nj][0]);  // 2 adds/addr: commutative
                atomicAdd(&cs_sm[wn + nj * 8 + c2 + 1], cs[nj][1]);
            }
        }
        __syncthreads();   // also guarantees all ldsm reads of buf (nc&1) are done
        if (tid < 128)
            csP[((size_t)z * 16 + mtile) * Sc + nc * 128 + tid] = cs_sm[tid];

        if (nc + 2 < 16) stage_k(nc & 1, nc + 2);
        CP_COMMIT();
    }
}

// ======================= attn@V: plain fp16 NT GEMM =========================
#define AV_A_BYTES (128 * 40 * 2)   // 10240
#define AV_B_BYTES (64 * 40 * 2)    // 5120

__global__ void __launch_bounds__(256, 2)
gemm_av_h(const __half* __restrict__ P, const __half* __restrict__ VH,
          float* __restrict__ out)
{
    __shared__ __half sm[3 * (128 + 64) * 40];

    const int z = blockIdx.z;
    const __half* A  = P  + (size_t)z * Sc * Sc;
    const __half* Bm = VH + (size_t)z * DHc * Sc;

    const int tid  = threadIdx.x;
    const int wid  = tid >> 5;
    const int lane = tid & 31;
    const int m0   = blockIdx.y * 128;
    const int wm   = (wid & 1) * 64;
    const int wn   = (wid >> 1) * 16;

    const uint32_t smBase = smem_u32(sm);

    float acc[4][2][4];
    #pragma unroll
    for (int i = 0; i < 4; ++i)
        #pragma unroll
        for (int j = 0; j < 2; ++j)
            #pragma unroll
            for (int p = 0; p < 4; ++p) acc[i][j][p] = 0.f;

    const int nk = Sc / 32;   // 64

    auto stage = [&](int s, int kt) {
        const int kc = kt * 32;
        const uint32_t base = smBase + s * (AV_A_BYTES + AV_B_BYTES);
        #pragma unroll
        for (int i = 0; i < 3; ++i) {
            const int id = tid + i * 256;
            if (id < 512) {
                const int r = id >> 2, c = (id & 3) * 8;
                CP_ASYNC16(base + (uint32_t)(r * 80 + c * 2),
                           &A[(size_t)(m0 + r) * Sc + kc + c]);
            } else {
                const int id2 = id - 512;
                const int r = id2 >> 2, c = (id2 & 3) * 8;
                CP_ASYNC16(base + AV_A_BYTES + (uint32_t)(r * 80 + c * 2),
                           &Bm[(size_t)r * Sc + kc + c]);
            }
        }
    };

    stage(0, 0); CP_COMMIT();
    stage(1, 1); CP_COMMIT();

    const int lrow = lane & 15;
    const int lcol = (lane >> 4) * 8;

    for (int kt = 0; kt < nk; ++kt) {
        CP_WAIT1();
        __syncthreads();

        const uint32_t aBase = smBase + (kt % 3) * (AV_A_BYTES + AV_B_BYTES);
        const uint32_t bBase = aBase + AV_A_BYTES;

        #pragma unroll
        for (int ks = 0; ks < 32; ks += 16) {
            uint32_t a[4][4];
            #pragma unroll
            for (int mi = 0; mi < 4; ++mi) {
                const uint32_t ad = aBase + (uint32_t)(wm + mi * 16 + lrow) * 80
                                          + (uint32_t)(ks + lcol) * 2;
                ldsm_x4(a[mi][0], a[mi][1], a[mi][2], a[mi][3], ad);
            }
            uint32_t b[4];
            const uint32_t bd = bBase + (uint32_t)(wn + lrow) * 80
                                      + (uint32_t)(ks + lcol) * 2;
            ldsm_x4(b[0], b[1], b[2], b[3], bd);
            #pragma unroll
            for (int mi = 0; mi < 4; ++mi)
                #pragma unroll
                for (int nj = 0; nj < 2; ++nj)
                    mma16816h(acc[mi][nj], a[mi], b[nj], b[nj + 2]);
        }

        if (kt + 2 < nk) stage((kt + 2) % 3, kt + 2);
        CP_COMMIT();
    }

    const int b = z / Hc, h = z % Hc;
    const int r4 = lane >> 2;
    const int c2 = (lane & 3) * 2;
    #pragma unroll
    for (int mi = 0; mi < 4; ++mi) {
        #pragma unroll
        for (int half = 0; half < 2; ++half) {
            const int s = m0 + wm + mi * 16 + r4 + half * 8;
            #pragma unroll
            for (int nj = 0; nj < 2; ++nj) {
                const int d = wn + nj * 8 + c2;
                float2 v = make_float2(acc[mi][nj][half * 2], acc[mi][nj][half * 2 + 1]);
                *reinterpret_cast<float2*>(&out[((size_t)b * Sc + s) * Dc + h * DHc + d]) = v;
            }
        }
    }
}

// ======================= small kernels ======================================
__global__ void cvt_h(const float* __restrict__ src, __half* __restrict__ dst)
{
    const size_t i = ((size_t)blockIdx.x * 256 + threadIdx.x) * 2;
    const float2 v = *reinterpret_cast<const float2*>(&src[i]);
    *reinterpret_cast<__half2*>(&dst[i]) = __floats2half2_rn(v.x, v.y);
}

__global__ void maskpack_kernel(const int* __restrict__ mask, uint32_t* __restrict__ mb)
{
    const size_t w = (size_t)blockIdx.x * 256 + threadIdx.x;
    const int4* p = reinterpret_cast<const int4*>(mask + w * 32);
    uint32_t bits = 0;
    #pragma unroll
    for (int i = 0; i < 8; ++i) {
        const int4 v = p[i];
        bits |= (v.x ? 1u : 0u) << (i * 4);
        bits |= (v.y ? 1u : 0u) << (i * 4 + 1);
        bits |= (v.z ? 1u : 0u) << (i * 4 + 2);
        bits |= (v.w ? 1u : 0u) << (i * 4 + 3);
    }
    mb[w] = bits;
}

__global__ void colsum_kernel(const float* __restrict__ csp, float* __restrict__ colsum)
{
    const size_t i = (size_t)blockIdx.x * 256 + threadIdx.x;   // z*Sc + t
    const size_t z = i >> 11;
    const int    t = (int)(i & 2047);
    float s = 0.f;
    #pragma unroll
    for (int my = 0; my < 16; ++my)
        s += csp[(z * 16 + my) * Sc + t];
    colsum[i] = s;
}

__global__ void vh_kernel(const float* __restrict__ vt, const float* __restrict__ colsum,
                          __half* __restrict__ vh)
{
    const size_t i = ((size_t)blockIdx.x * 256 + threadIdx.x) * 2;
    const size_t zd = i >> 11;
    const int    t  = (int)(i & 2047);
    const size_t z  = zd >> 6;
    const float2 v = *reinterpret_cast<const float2*>(&vt[i]);
    const float2 c = *reinterpret_cast<const float2*>(&colsum[z * Sc + t]);
    *reinterpret_cast<__half2*>(&vh[i]) =
        __floats2half2_rn(__fdividef(v.x, c.x), __fdividef(v.y, c.y));
}

// LN + residual. HOUT=0: fp32 out. HOUT=1: fp16 out.
template<int HOUT>
__global__ void ln_residual_kernel(const float* __restrict__ in,
                                   const float* __restrict__ gamma,
                                   const float* __restrict__ beta,
                                   float* __restrict__ out,
                                   __half* __restrict__ outH)
{
    const size_t row = blockIdx.x;
    const float* xr = in + row * Dc;
    const int tid = threadIdx.x;

    const float v0 = xr[tid], v1 = xr[tid + 256], v2 = xr[tid + 512];

    __shared__ float red[256];
    red[tid] = v0 + v1 + v2;
    __syncthreads();
    #pragma unroll
    for (int o = 128; o > 0; o >>= 1) {
        if (tid < o) red[tid] += red[tid + o];
        __syncthreads();
    }
    const float mu = red[0] * (1.f / Dc);
    __syncthreads();

    const float d0 = v0 - mu, d1 = v1 - mu, d2 = v2 - mu;
    red[tid] = d0 * d0 + d1 * d1 + d2 * d2;
    __syncthreads();
    #pragma unroll
    for (int o = 128; o > 0; o >>= 1) {
        if (tid < o) red[tid] += red[tid + o];
        __syncthreads();
    }
    const float rstd = rsqrtf(red[0] * (1.f / Dc) + 1e-5f);

    const float o0 = d0 * rstd * gamma[tid]       + beta[tid]       + v0;
    const float o1 = d1 * rstd * gamma[tid + 256] + beta[tid + 256] + v1;
    const float o2 = d2 * rstd * gamma[tid + 512] + beta[tid + 512] + v2;

    if (HOUT == 0) {
        float* orow = out + row * Dc;
        orow[tid] = o0; orow[tid + 256] = o1; orow[tid + 512] = o2;
    } else {
        __half* orow = outH + row * Dc;
        orow[tid]       = __float2half(o0);
        orow[tid + 256] = __float2half(o1);
        orow[tid + 512] = __float2half(o2);
    }
}

// ---------------------------------------------------------------------------
extern "C" void kernel_launch(void* const* d_in, const int* in_sizes, int n_in,
                              void* d_out, int out_size)
{
    (void)in_sizes; (void)n_in; (void)out_size;
    const float* x    = (const float*)d_in[0];
    const int*   mask = (const int*)d_in[1];
    const float* Wq = (const float*)d_in[2];
    const float* bq = (const float*)d_in[3];
    const float* Wk = (const float*)d_in[4];
    const float* bk = (const float*)d_in[5];
    const float* Wv = (const float*)d_in[6];
    const float* bv = (const float*)d_in[7];
    const float* gamma = (const float*)d_in[8];
    const float* beta  = (const float*)d_in[9];
    const float* W1 = (const float*)d_in[10];
    const float* b1 = (const float*)d_in[11];
    const float* W2 = (const float*)d_in[12];
    const float* b2 = (const float*)d_in[13];
    float* out = (float*)d_out;

    float *vt, *a, *bb, *csp, *colsum;
    __half *ph, *vh;
    uint32_t *mb;
    cudaGetSymbolAddress((void**)&vt,     g_vt);
    cudaGetSymbolAddress((void**)&a,      g_a);
    cudaGetSymbolAddress((void**)&bb,     g_b);
    cudaGetSymbolAddress((void**)&csp,    g_csp);
    cudaGetSymbolAddress((void**)&colsum, g_colsum);
    cudaGetSymbolAddress((void**)&ph,     g_ph);
    cudaGetSymbolAddress((void**)&vh,     g_vh);
    cudaGetSymbolAddress((void**)&mb,     g_mb);

    __half *xh, *ah, *hh, *qh, *kh, *wqh, *wkh, *wvh, *w1h, *w2h;
    cudaGetSymbolAddress((void**)&xh,  g_xh);
    cudaGetSymbolAddress((void**)&ah,  g_ah);
    cudaGetSymbolAddress((void**)&hh,  g_hh);
    cudaGetSymbolAddress((void**)&qh,  g_qh);
    cudaGetSymbolAddress((void**)&kh,  g_kh);
    cudaGetSymbolAddress((void**)&wqh, g_wqh);
    cudaGetSymbolAddress((void**)&wkh, g_wkh);
    cudaGetSymbolAddress((void**)&wvh, g_wvh);
    cudaGetSymbolAddress((void**)&w1h, g_w1h);
    cudaGetSymbolAddress((void**)&w2h, g_w2h);

    cudaFuncSetAttribute(gemm_mma<0>, cudaFuncAttributeMaxDynamicSharedMemorySize, GEMM_SMEM);
    cudaFuncSetAttribute(gemm_mma<1>, cudaFuncAttributeMaxDynamicSharedMemorySize, GEMM_SMEM);
    cudaFuncSetAttribute(gemm_mma<3>, cudaFuncAttributeMaxDynamicSharedMemorySize, GEMM_SMEM);
    cudaFuncSetAttribute(gemm_mma<5>, cudaFuncAttributeMaxDynamicSharedMemorySize, GEMM_SMEM);
    cudaFuncSetAttribute(scores_fused, cudaFuncAttributeMaxDynamicSharedMemorySize, SCORES_SMEM);

    const int MS = Bc * Sc;               // 8192
    const float scale = 1.0f / sqrtf((float)Sc);

    // 0) mask bit-pack + fp16 conversions
    maskpack_kernel<<<(Bc * Sc * (Sc / 32)) / 256, 256>>>(mask, mb);
    cvt_h<<<(MS * Ec) / 512, 256>>>(x,  xh);
    cvt_h<<<(Dc * Ec) / 512, 256>>>(Wq, wqh);
    cvt_h<<<(Dc * Ec) / 512, 256>>>(Wk, wkh);
    cvt_h<<<(Dc * Ec) / 512, 256>>>(Wv, wvh);
    cvt_h<<<(Fc * Dc) / 512, 256>>>(W1, w1h);
    cvt_h<<<(Dc * Fc) / 512, 256>>>(W2, w2h);

    // 1) QKV projections
    {
        dim3 grid(Dc / 128, MS / 128);
        gemm_mma<5><<<grid, 256, GEMM_SMEM>>>(xh, wqh, Dc, Ec, 0, 0, bq, nullptr, qh);
        gemm_mma<5><<<grid, 256, GEMM_SMEM>>>(xh, wkh, Dc, Ec, 0, 0, bk, nullptr, kh);
        gemm_mma<3><<<grid, 256, GEMM_SMEM>>>(xh, wvh, Dc, Ec, 0, 0, bv, vt, nullptr);
    }

    // 2) p = exp(masked scores) fp16 + column partial sums (q-resident kernel)
    {
        dim3 grid(16, Bc * Hc);
        scores_fused<<<grid, 256, SCORES_SMEM>>>(qh, kh, mb, scale, ph, csp);
    }

    // 3) column sums + normalized V (fp16)
    colsum_kernel<<<(Bc * Hc * Sc) / 256, 256>>>(csp, colsum);
    vh_kernel<<<(Bc * Hc * DHc * Sc) / 512, 256>>>(vt, colsum, vh);

    // 4) o = p @ vh^T -> concat heads
    {
        dim3 grid(1, Sc / 128, Bc * Hc);
        gemm_av_h<<<grid, 256>>>(ph, vh, a);
    }

    // 5) a = LN(a) + a  -> fp16
    ln_residual_kernel<1><<<MS, 256>>>(a, gamma, beta, nullptr, ah);

    // 6) h = relu(a @ W1^T + b1) -> fp16
    {
        dim3 grid(Fc / 128, MS / 128);
        gemm_mma<1><<<grid, 256, GEMM_SMEM>>>(ah, w1h, Fc, Dc, 0, 0, b1, nullptr, hh);
    }

    // 7) bb = h @ W2^T + b2
    {
        dim3 grid(Dc / 128, MS / 128);
        gemm_mma<0><<<grid, 256, GEMM_SMEM>>>(hh, w2h, Dc, Fc, 0, 0, b2, bb, nullptr);
    }

    // 8) out = LN(bb) + bb
    ln_residual_kernel<0><<<MS, 256>>>(bb, gamma, beta, out, nullptr);
}

// round 12
// speedup vs baseline: 1.0518x; 1.0518x over previous
#include <cuda_runtime.h>
#include <cuda_bf16.h>
#include <cuda_fp16.h>
#include <math.h>
#include <stdint.h>

// Problem dims (fixed by the reference)
#define Bc  4
#define Sc  2048
#define Ec  768
#define Dc  768
#define Hc  12
#define DHc 64
#define Fc  3072

#define LDSH 40                      // fp16 per smem row (80 B pitch)
#define STAGE_BYTES (128 * LDSH * 2) // one matrix, one stage = 10240 B
#define GEMM_SMEM (3 * 2 * STAGE_BYTES)

#define QKH_STRIDE ((size_t)Bc*Hc*Sc*DHc)

// ---------------- scratch (device globals: allocation-free) ----------------
__device__ float    g_vt[(size_t)Bc*Hc*DHc*Sc];       // [B,H,dh,S] fp32
__device__ __half   g_ph[(size_t)Bc*Hc*Sc*Sc];        // p = exp(masked score) fp16
__device__ __half   g_vh[(size_t)Bc*Hc*DHc*Sc];       // v / colsum, fp16
__device__ float    g_csp[(size_t)Bc*Hc*16*Sc];       // per-mtile column partial sums
__device__ float    g_colsum[(size_t)Bc*Hc*Sc];
__device__ uint32_t g_mb[(size_t)Bc*Sc*(Sc/32)];      // bit-packed mask
__device__ float    g_a [(size_t)Bc*Sc*Dc];
__device__ float    g_b [(size_t)Bc*Sc*Dc];

// fp16 operand buffers
__device__ __half g_xh  [(size_t)Bc*Sc*Ec];
__device__ __half g_ah  [(size_t)Bc*Sc*Dc];           // post-LN1 fp16
__device__ __half g_hh  [(size_t)Bc*Sc*Fc];           // hidden fp16
__device__ __half g_qkh [2*QKH_STRIDE];               // q then k
__device__ __half g_wqkv[(size_t)3*Dc*Ec];            // Wq;Wk;Wv combined
__device__ float  g_bqkv[3*Dc];                       // bq;bk;bv combined
__device__ __half g_w1h [(size_t)Fc*Dc];
__device__ __half g_w2h [(size_t)Dc*Fc];

// ======================= warp-MMA helpers ===================================
__device__ __forceinline__ uint32_t smem_u32(const void* p) {
    uint32_t a;
    asm("{ .reg .u64 t; cvta.to.shared.u64 t, %1; cvt.u32.u64 %0, t; }" : "=r"(a) : "l"(p));
    return a;
}
__device__ __forceinline__ void ldsm_x4(uint32_t& r0, uint32_t& r1, uint32_t& r2, uint32_t& r3,
                                        uint32_t addr) {
    asm volatile("ldmatrix.sync.aligned.m8n8.x4.shared.b16 {%0,%1,%2,%3}, [%4];"
                 : "=r"(r0), "=r"(r1), "=r"(r2), "=r"(r3) : "r"(addr));
}
__device__ __forceinline__ void mma16816h(float* d, const uint32_t* a, uint32_t b0, uint32_t b1) {
    asm volatile("mma.sync.aligned.m16n8k16.row.col.f32.f16.f16.f32 "
                 "{%0,%1,%2,%3}, {%4,%5,%6,%7}, {%8,%9}, {%0,%1,%2,%3};"
                 : "+f"(d[0]), "+f"(d[1]), "+f"(d[2]), "+f"(d[3])
                 : "r"(a[0]), "r"(a[1]), "r"(a[2]), "r"(a[3]), "r"(b0), "r"(b1));
}
#define CP_ASYNC16(dst, src) \
    asm volatile("cp.async.cg.shared.global [%0], [%1], 16;" :: "r"(dst), "l"(src))
#define CP_COMMIT() asm volatile("cp.async.commit_group;")
#define CP_WAIT1()  asm volatile("cp.async.wait_group 1;")

// ======================= fp16 NT GEMM via mma.sync ==========================
// C[M,N] = A[M,K] @ B[N,K]^T (fp16 operands, fp32 accumulate), batched via z.
// Tile 128x128x32, 3-stage cp.async, 8 warps (2M x 4N), warp tile 64x32.
// EPI: 0 = +bias -> outF[m*N+n]
//      1 = relu(+bias) -> fp16 outH[m*N+n]
//      4 = scores: p = mask ? 0 : exp(acc*scale) -> fp16 outH; col partials -> csP
//      7 = fused QKV: seg=n/768 -> 0: q scatter fp16, 1: k scatter fp16,
//          2: v scatter fp32 [b,h,d,s]; all +bias[n]
template<int EPI>
__global__ void __launch_bounds__(256, 2)
gemm_mma(const __half* __restrict__ A, const __half* __restrict__ Bw,
         int N, int Kp, long strideA, long strideB,
         const float* __restrict__ bias, const uint32_t* __restrict__ mb, float scale,
         float* __restrict__ outF, __half* __restrict__ outH,
         float* __restrict__ csP)
{
    extern __shared__ char dynsm[];
    __shared__ float cs_sm[128];

    const int z = blockIdx.z;
    A  += (size_t)z * strideA;
    Bw += (size_t)z * strideB;

    const int tid  = threadIdx.x;
    const int wid  = tid >> 5;
    const int lane = tid & 31;
    const int m0   = blockIdx.y * 128;
    const int n0   = blockIdx.x * 128;
    const int wm   = (wid & 1) * 64;
    const int wn   = (wid >> 1) * 32;

    const uint32_t smBase = smem_u32(dynsm);

    float acc[4][4][4];
    #pragma unroll
    for (int i = 0; i < 4; ++i)
        #pragma unroll
        for (int j = 0; j < 4; ++j)
            #pragma unroll
            for (int p = 0; p < 4; ++p) acc[i][j][p] = 0.f;

    const int nk = Kp / 32;

    auto stage = [&](int s, int kt) {
        const int kc = kt * 32;
        const uint32_t base = smBase + s * (2 * STAGE_BYTES);
        #pragma unroll
        for (int i = 0; i < 2; ++i) {
            const int id = tid + i * 256;
            const int r  = id >> 2;
            const int c  = (id & 3) * 8;
            const uint32_t dA = base + (uint32_t)(r * 80 + c * 2);
            const uint32_t dB = dA + STAGE_BYTES;
            CP_ASYNC16(dA, &A [(size_t)(m0 + r) * Kp + kc + c]);
            CP_ASYNC16(dB, &Bw[(size_t)(n0 + r) * Kp + kc + c]);
        }
    };

    stage(0, 0); CP_COMMIT();
    stage(1, 1); CP_COMMIT();

    const int lrow = lane & 15;
    const int lcol = (lane >> 4) * 8;

    for (int kt = 0; kt < nk; ++kt) {
        CP_WAIT1();
        __syncthreads();

        const uint32_t aBase = smBase + (kt % 3) * (2 * STAGE_BYTES);
        const uint32_t bBase = aBase + STAGE_BYTES;

        #pragma unroll
        for (int ks = 0; ks < 32; ks += 16) {
            uint32_t a[4][4];
            #pragma unroll
            for (int mi = 0; mi < 4; ++mi) {
                const uint32_t ad = aBase + (uint32_t)(wm + mi * 16 + lrow) * 80
                                          + (uint32_t)(ks + lcol) * 2;
                ldsm_x4(a[mi][0], a[mi][1], a[mi][2], a[mi][3], ad);
            }
            uint32_t b[2][4];
            #pragma unroll
            for (int bj = 0; bj < 2; ++bj) {
                const uint32_t bd = bBase + (uint32_t)(wn + bj * 16 + lrow) * 80
                                          + (uint32_t)(ks + lcol) * 2;
                ldsm_x4(b[bj][0], b[bj][1], b[bj][2], b[bj][3], bd);
            }
            #pragma unroll
            for (int mi = 0; mi < 4; ++mi)
                #pragma unroll
                for (int nj = 0; nj < 4; ++nj)
                    mma16816h(acc[mi][nj], a[mi], b[nj >> 1][nj & 1], b[nj >> 1][(nj & 1) + 2]);
        }

        if (kt + 2 < nk) stage((kt + 2) % 3, kt + 2);
        CP_COMMIT();
    }

    // ---------------- epilogue ----------------
    const int r4 = lane >> 2;
    const int c2 = (lane & 3) * 2;

    float cs[4][2];
    #pragma unroll
    for (int nj = 0; nj < 4; ++nj) { cs[nj][0] = 0.f; cs[nj][1] = 0.f; }

    const int seg7 = n0 / Ec;   // EPI 7: 0=q, 1=k, 2=v (tiles never straddle)

    #pragma unroll
    for (int mi = 0; mi < 4; ++mi) {
        #pragma unroll
        for (int half = 0; half < 2; ++half) {
            const int m = m0 + wm + mi * 16 + r4 + half * 8;
            uint32_t word = 0;
            if (EPI == 4) {
                const int bq = z / Hc;
                word = mb[((size_t)bq * Sc + m) * (Sc / 32) + (size_t)(n0 + wn) / 32];
            }
            #pragma unroll
            for (int nj = 0; nj < 4; ++nj) {
                const int n = n0 + wn + nj * 8 + c2;
                float v0 = acc[mi][nj][half * 2];
                float v1 = acc[mi][nj][half * 2 + 1];
                if (EPI != 4) { v0 += bias[n]; v1 += bias[n + 1]; }
                if (EPI == 0) {
                    *reinterpret_cast<float2*>(&outF[(size_t)m * N + n]) = make_float2(v0, v1);
                } else if (EPI == 1) {
                    *reinterpret_cast<__half2*>(&outH[(size_t)m * N + n]) =
                        __floats2half2_rn(fmaxf(v0, 0.f), fmaxf(v1, 0.f));
                } else if (EPI == 4) {
                    const int bit0 = (word >> (n & 31)) & 1;
                    const int bit1 = (word >> ((n + 1) & 31)) & 1;
                    const float e0 = bit0 ? 0.f : __expf(v0 * scale);
                    const float e1 = bit1 ? 0.f : __expf(v1 * scale);
                    *reinterpret_cast<__half2*>(&outH[((size_t)z * Sc + m) * Sc + n]) =
                        __floats2half2_rn(e0, e1);
                    cs[nj][0] += e0; cs[nj][1] += e1;
                } else { // EPI 7: fused QKV
                    const int col = n - seg7 * Ec;
                    const int b = m >> 11, s = m & 2047;
                    const int h = col >> 6, d = col & 63;
                    if (seg7 < 2) {
                        *reinterpret_cast<__half2*>(
                            &outH[seg7 * QKH_STRIDE +
                                  (((size_t)b * Hc + h) * Sc + s) * DHc + d]) =
                            __floats2half2_rn(v0, v1);
                    } else {
                        outF[(((size_t)b * Hc + h) * DHc + d)     * Sc + s] = v0;
                        outF[(((size_t)b * Hc + h) * DHc + d + 1) * Sc + s] = v1;
                    }
                }
            }
        }
    }

    if (EPI == 4) {
        #pragma unroll
        for (int nj = 0; nj < 4; ++nj)
            #pragma unroll
            for (int p = 0; p < 2; ++p) {
                float v = cs[nj][p];
                v += __shfl_xor_sync(0xffffffffu, v, 4);
                v += __shfl_xor_sync(0xffffffffu, v, 8);
                v += __shfl_xor_sync(0xffffffffu, v, 16);
                cs[nj][p] = v;
            }
        if (tid < 128) cs_sm[tid] = 0.f;
        __syncthreads();
        if (r4 == 0) {
            #pragma unroll
            for (int nj = 0; nj < 4; ++nj) {
                atomicAdd(&cs_sm[wn + nj * 8 + c2],     cs[nj][0]);  // 2 adds/addr: commutative
                atomicAdd(&cs_sm[wn + nj * 8 + c2 + 1], cs[nj][1]);
            }
        }
        __syncthreads();
        if (tid < 128)
            csP[((size_t)z * 16 + blockIdx.y) * Sc + n0 + tid] = cs_sm[tid];
    }
}

// ======================= attn@V: plain fp16 NT GEMM =========================
#define AV_A_BYTES (128 * 40 * 2)   // 10240
#define AV_B_BYTES (64 * 40 * 2)    // 5120

__global__ void __launch_bounds__(256, 2)
gemm_av_h(const __half* __restrict__ P, const __half* __restrict__ VH,
          float* __restrict__ out)
{
    __shared__ __half sm[3 * (128 + 64) * 40];

    const int z = blockIdx.z;
    const __half* A  = P  + (size_t)z * Sc * Sc;
    const __half* Bm = VH + (size_t)z * DHc * Sc;

    const int tid  = threadIdx.x;
    const int wid  = tid >> 5;
    const int lane = tid & 31;
    const int m0   = blockIdx.y * 128;
    const int wm   = (wid & 1) * 64;
    const int wn   = (wid >> 1) * 16;

    const uint32_t smBase = smem_u32(sm);

    float acc[4][2][4];
    #pragma unroll
    for (int i = 0; i < 4; ++i)
        #pragma unroll
        for (int j = 0; j < 2; ++j)
            #pragma unroll
            for (int p = 0; p < 4; ++p) acc[i][j][p] = 0.f;

    const int nk = Sc / 32;   // 64

    auto stage = [&](int s, int kt) {
        const int kc = kt * 32;
        const uint32_t base = smBase + s * (AV_A_BYTES + AV_B_BYTES);
        #pragma unroll
        for (int i = 0; i < 3; ++i) {
            const int id = tid + i * 256;
            if (id < 512) {
                const int r = id >> 2, c = (id & 3) * 8;
                CP_ASYNC16(base + (uint32_t)(r * 80 + c * 2),
                           &A[(size_t)(m0 + r) * Sc + kc + c]);
            } else {
                const int id2 = id - 512;
                const int r = id2 >> 2, c = (id2 & 3) * 8;
                CP_ASYNC16(base + AV_A_BYTES + (uint32_t)(r * 80 + c * 2),
                           &Bm[(size_t)r * Sc + kc + c]);
            }
        }
    };

    stage(0, 0); CP_COMMIT();
    stage(1, 1); CP_COMMIT();

    const int lrow = lane & 15;
    const int lcol = (lane >> 4) * 8;

    for (int kt = 0; kt < nk; ++kt) {
        CP_WAIT1();
        __syncthreads();

        const uint32_t aBase = smBase + (kt % 3) * (AV_A_BYTES + AV_B_BYTES);
        const uint32_t bBase = aBase + AV_A_BYTES;

        #pragma unroll
        for (int ks = 0; ks < 32; ks += 16) {
            uint32_t a[4][4];
            #pragma unroll
            for (int mi = 0; mi < 4; ++mi) {
                const uint32_t ad = aBase + (uint32_t)(wm + mi * 16 + lrow) * 80
                                          + (uint32_t)(ks + lcol) * 2;
                ldsm_x4(a[mi][0], a[mi][1], a[mi][2], a[mi][3], ad);
            }
            uint32_t b[4];
            const uint32_t bd = bBase + (uint32_t)(wn + lrow) * 80
                                      + (uint32_t)(ks + lcol) * 2;
            ldsm_x4(b[0], b[1], b[2], b[3], bd);
            #pragma unroll
            for (int mi = 0; mi < 4; ++mi)
                #pragma unroll
                for (int nj = 0; nj < 2; ++nj)
                    mma16816h(acc[mi][nj], a[mi], b[nj], b[nj + 2]);
        }

        if (kt + 2 < nk) stage((kt + 2) % 3, kt + 2);
        CP_COMMIT();
    }

    const int b = z / Hc, h = z % Hc;
    const int r4 = lane >> 2;
    const int c2 = (lane & 3) * 2;
    #pragma unroll
    for (int mi = 0; mi < 4; ++mi) {
        #pragma unroll
        for (int half = 0; half < 2; ++half) {
            const int s = m0 + wm + mi * 16 + r4 + half * 8;
            #pragma unroll
            for (int nj = 0; nj < 2; ++nj) {
                const int d = wn + nj * 8 + c2;
                float2 v = make_float2(acc[mi][nj][half * 2], acc[mi][nj][half * 2 + 1]);
                *reinterpret_cast<float2*>(&out[((size_t)b * Sc + s) * Dc + h * DHc + d]) = v;
            }
        }
    }
}

// ======================= small kernels ======================================
__global__ void cvt_h(const float* __restrict__ src, __half* __restrict__ dst)
{
    const size_t i = ((size_t)blockIdx.x * 256 + threadIdx.x) * 2;
    const float2 v = *reinterpret_cast<const float2*>(&src[i]);
    *reinterpret_cast<__half2*>(&dst[i]) = __floats2half2_rn(v.x, v.y);
}

__global__ void maskpack_kernel(const int* __restrict__ mask, uint32_t* __restrict__ mb)
{
    const size_t w = (size_t)blockIdx.x * 256 + threadIdx.x;
    const int4* p = reinterpret_cast<const int4*>(mask + w * 32);
    uint32_t bits = 0;
    #pragma unroll
    for (int i = 0; i < 8; ++i) {
        const int4 v = p[i];
        bits |= (v.x ? 1u : 0u) << (i * 4);
        bits |= (v.y ? 1u : 0u) << (i * 4 + 1);
        bits |= (v.z ? 1u : 0u) << (i * 4 + 2);
        bits |= (v.w ? 1u : 0u) << (i * 4 + 3);
    }
    mb[w] = bits;
}

__global__ void colsum_kernel(const float* __restrict__ csp, float* __restrict__ colsum)
{
    const size_t i = (size_t)blockIdx.x * 256 + threadIdx.x;   // z*Sc + t
    const size_t z = i >> 11;
    const int    t = (int)(i & 2047);
    float s = 0.f;
    #pragma unroll
    for (int my = 0; my < 16; ++my)
        s += csp[(z * 16 + my) * Sc + t];
    colsum[i] = s;
}

__global__ void vh_kernel(const float* __restrict__ vt, const float* __restrict__ colsum,
                          __half* __restrict__ vh)
{
    const size_t i = ((size_t)blockIdx.x * 256 + threadIdx.x) * 2;
    const size_t zd = i >> 11;
    const int    t  = (int)(i & 2047);
    const size_t z  = zd >> 6;
    const float2 v = *reinterpret_cast<const float2*>(&vt[i]);
    const float2 c = *reinterpret_cast<const float2*>(&colsum[z * Sc + t]);
    *reinterpret_cast<__half2*>(&vh[i]) =
        __floats2half2_rn(__fdividef(v.x, c.x), __fdividef(v.y, c.y));
}

// LN + residual. HOUT=0: fp32 out. HOUT=1: fp16 out.
template<int HOUT>
__global__ void ln_residual_kernel(const float* __restrict__ in,
                                   const float* __restrict__ gamma,
                                   const float* __restrict__ beta,
                                   float* __restrict__ out,
                                   __half* __restrict__ outH)
{
    const size_t row = blockIdx.x;
    const float* xr = in + row * Dc;
    const int tid = threadIdx.x;

    const float v0 = xr[tid], v1 = xr[tid + 256], v2 = xr[tid + 512];

    __shared__ float red[256];
    red[tid] = v0 + v1 + v2;
    __syncthreads();
    #pragma unroll
    for (int o = 128; o > 0; o >>= 1) {
        if (tid < o) red[tid] += red[tid + o];
        __syncthreads();
    }
    const float mu = red[0] * (1.f / Dc);
    __syncthreads();

    const float d0 = v0 - mu, d1 = v1 - mu, d2 = v2 - mu;
    red[tid] = d0 * d0 + d1 * d1 + d2 * d2;
    __syncthreads();
    #pragma unroll
    for (int o = 128; o > 0; o >>= 1) {
        if (tid < o) red[tid] += red[tid + o];
        __syncthreads();
    }
    const float rstd = rsqrtf(red[0] * (1.f / Dc) + 1e-5f);

    const float o0 = d0 * rstd * gamma[tid]       + beta[tid]       + v0;
    const float o1 = d1 * rstd * gamma[tid + 256] + beta[tid + 256] + v1;
    const float o2 = d2 * rstd * gamma[tid + 512] + beta[tid + 512] + v2;

    if (HOUT == 0) {
        float* orow = out + row * Dc;
        orow[tid] = o0; orow[tid + 256] = o1; orow[tid + 512] = o2;
    } else {
        __half* orow = outH + row * Dc;
        orow[tid]       = __float2half(o0);
        orow[tid + 256] = __float2half(o1);
        orow[tid + 512] = __float2half(o2);
    }
}

// ---------------------------------------------------------------------------
extern "C" void kernel_launch(void* const* d_in, const int* in_sizes, int n_in,
                              void* d_out, int out_size)
{
    (void)in_sizes; (void)n_in; (void)out_size;
    const float* x    = (const float*)d_in[0];
    const int*   mask = (const int*)d_in[1];
    const float* Wq = (const float*)d_in[2];
    const float* bq = (const float*)d_in[3];
    const float* Wk = (const float*)d_in[4];
    const float* bk = (const float*)d_in[5];
    const float* Wv = (const float*)d_in[6];
    const float* bv = (const float*)d_in[7];
    const float* gamma = (const float*)d_in[8];
    const float* beta  = (const float*)d_in[9];
    const float* W1 = (const float*)d_in[10];
    const float* b1 = (const float*)d_in[11];
    const float* W2 = (const float*)d_in[12];
    const float* b2 = (const float*)d_in[13];
    float* out = (float*)d_out;

    float *vt, *a, *bb, *csp, *colsum, *bqkv;
    __half *ph, *vh;
    uint32_t *mb;
    cudaGetSymbolAddress((void**)&vt,     g_vt);
    cudaGetSymbolAddress((void**)&a,      g_a);
    cudaGetSymbolAddress((void**)&bb,     g_b);
    cudaGetSymbolAddress((void**)&csp,    g_csp);
    cudaGetSymbolAddress((void**)&colsum, g_colsum);
    cudaGetSymbolAddress((void**)&ph,     g_ph);
    cudaGetSymbolAddress((void**)&vh,     g_vh);
    cudaGetSymbolAddress((void**)&mb,     g_mb);
    cudaGetSymbolAddress((void**)&bqkv,   g_bqkv);

    __half *xh, *ah, *hh, *qkh, *wqkv, *w1h, *w2h;
    cudaGetSymbolAddress((void**)&xh,   g_xh);
    cudaGetSymbolAddress((void**)&ah,   g_ah);
    cudaGetSymbolAddress((void**)&hh,   g_hh);
    cudaGetSymbolAddress((void**)&qkh,  g_qkh);
    cudaGetSymbolAddress((void**)&wqkv, g_wqkv);
    cudaGetSymbolAddress((void**)&w1h,  g_w1h);
    cudaGetSymbolAddress((void**)&w2h,  g_w2h);

    cudaFuncSetAttribute(gemm_mma<0>, cudaFuncAttributeMaxDynamicSharedMemorySize, GEMM_SMEM);
    cudaFuncSetAttribute(gemm_mma<1>, cudaFuncAttributeMaxDynamicSharedMemorySize, GEMM_SMEM);
    cudaFuncSetAttribute(gemm_mma<4>, cudaFuncAttributeMaxDynamicSharedMemorySize, GEMM_SMEM);
    cudaFuncSetAttribute(gemm_mma<7>, cudaFuncAttributeMaxDynamicSharedMemorySize, GEMM_SMEM);

    const int MS = Bc * Sc;               // 8192
    const float scale = 1.0f / sqrtf((float)Sc);

    // 0) mask bit-pack, fp16 conversions, combined bias (d2d copies)
    maskpack_kernel<<<(Bc * Sc * (Sc / 32)) / 256, 256>>>(mask, mb);
    cvt_h<<<(MS * Ec) / 512, 256>>>(x,  xh);
    cvt_h<<<(Dc * Ec) / 512, 256>>>(Wq, wqkv);
    cvt_h<<<(Dc * Ec) / 512, 256>>>(Wk, wqkv + (size_t)Dc * Ec);
    cvt_h<<<(Dc * Ec) / 512, 256>>>(Wv, wqkv + (size_t)2 * Dc * Ec);
    cvt_h<<<(Fc * Dc) / 512, 256>>>(W1, w1h);
    cvt_h<<<(Dc * Fc) / 512, 256>>>(W2, w2h);
    cudaMemcpyAsync(bqkv,          bq, Dc * sizeof(float), cudaMemcpyDeviceToDevice);
    cudaMemcpyAsync(bqkv + Dc,     bk, Dc * sizeof(float), cudaMemcpyDeviceToDevice);
    cudaMemcpyAsync(bqkv + 2 * Dc, bv, Dc * sizeof(float), cudaMemcpyDeviceToDevice);

    // 1) fused QKV projection: one GEMM, N = 2304
    {
        dim3 grid(3 * Dc / 128, MS / 128);
        gemm_mma<7><<<grid, 256, GEMM_SMEM>>>(xh, wqkv, 3 * Dc, Ec, 0, 0,
                                              bqkv, nullptr, 0.f, vt, qkh, nullptr);
    }

    // 2) p = exp(masked scores) fp16 + per-tile column partial sums
    {
        dim3 grid(Sc / 128, Sc / 128, Bc * Hc);
        gemm_mma<4><<<grid, 256, GEMM_SMEM>>>(qkh, qkh + QKH_STRIDE, Sc, DHc,
                                              (long)Sc * DHc, (long)Sc * DHc,
                                              nullptr, mb, scale, nullptr, ph, csp);
    }

    // 3) column sums + normalized V (fp16)
    colsum_kernel<<<(Bc * Hc * Sc) / 256, 256>>>(csp, colsum);
    vh_kernel<<<(Bc * Hc * DHc * Sc) / 512, 256>>>(vt, colsum, vh);

    // 4) o = p @ vh^T -> concat heads
    {
        dim3 grid(1, Sc / 128, Bc * Hc);
        gemm_av_h<<<grid, 256>>>(ph, vh, a);
    }

    // 5) a = LN(a) + a  -> fp16
    ln_residual_kernel<1><<<MS, 256>>>(a, gamma, beta, nullptr, ah);

    // 6) h = relu(a @ W1^T + b1) -> fp16
    {
        dim3 grid(Fc / 128, MS / 128);
        gemm_mma<1><<<grid, 256, GEMM_SMEM>>>(ah, w1h, Fc, Dc, 0, 0, b1,
                                              nullptr, 0.f, nullptr, hh, nullptr);
    }

    // 7) bb = h @ W2^T + b2
    {
        dim3 grid(Dc / 128, MS / 128);
        gemm_mma<0><<<grid, 256, GEMM_SMEM>>>(hh, w2h, Dc, Fc, 0, 0, b2,
                                              nullptr, 0.f, bb, nullptr, nullptr);
    }

    // 8) out = LN(bb) + bb
    ln_residual_kernel<0><<<MS, 256>>>(bb, gamma, beta, out, nullptr);
}

// round 13
// speedup vs baseline: 1.1126x; 1.0578x over previous
#include <cuda_runtime.h>
#include <cuda_bf16.h>
#include <cuda_fp16.h>
#include <math.h>
#include <stdint.h>

// Problem dims (fixed by the reference)
#define Bc  4
#define Sc  2048
#define Ec  768
#define Dc  768
#define Hc  12
#define DHc 64
#define Fc  3072

#define QKH_STRIDE ((size_t)Bc*Hc*Sc*DHc)

// ---------------- scratch (device globals: allocation-free) ----------------
__device__ float    g_vt[(size_t)Bc*Hc*DHc*Sc];       // [B,H,dh,S] fp32
__device__ __half   g_ph[(size_t)Bc*Hc*Sc*Sc];        // p = exp(masked score) fp16
__device__ __half   g_vh[(size_t)Bc*Hc*DHc*Sc];       // v / colsum, fp16
__device__ float    g_csp[(size_t)Bc*Hc*16*Sc];       // per-mtile column partial sums
__device__ float    g_colsum[(size_t)Bc*Hc*Sc];
__device__ uint32_t g_mb[(size_t)Bc*Sc*(Sc/32)];      // bit-packed mask
__device__ float    g_a [(size_t)Bc*Sc*Dc];
__device__ float    g_b [(size_t)Bc*Sc*Dc];

// fp16 operand buffers
__device__ __half g_xh  [(size_t)Bc*Sc*Ec];
__device__ __half g_ah  [(size_t)Bc*Sc*Dc];           // post-LN1 fp16
__device__ __half g_hh  [(size_t)Bc*Sc*Fc];           // hidden fp16
__device__ __half g_qkh [2*QKH_STRIDE];               // q then k
__device__ __half g_wqkv[(size_t)3*Dc*Ec];            // Wq;Wk;Wv combined
__device__ float  g_bqkv[3*Dc];                       // bq;bk;bv combined
__device__ __half g_w1h [(size_t)Fc*Dc];
__device__ __half g_w2h [(size_t)Dc*Fc];

// ======================= warp-MMA helpers ===================================
__device__ __forceinline__ uint32_t smem_u32(const void* p) {
    uint32_t a;
    asm("{ .reg .u64 t; cvta.to.shared.u64 t, %1; cvt.u32.u64 %0, t; }" : "=r"(a) : "l"(p));
    return a;
}
__device__ __forceinline__ void ldsm_x4(uint32_t& r0, uint32_t& r1, uint32_t& r2, uint32_t& r3,
                                        uint32_t addr) {
    asm volatile("ldmatrix.sync.aligned.m8n8.x4.shared.b16 {%0,%1,%2,%3}, [%4];"
                 : "=r"(r0), "=r"(r1), "=r"(r2), "=r"(r3) : "r"(addr));
}
__device__ __forceinline__ void mma16816h(float* d, const uint32_t* a, uint32_t b0, uint32_t b1) {
    asm volatile("mma.sync.aligned.m16n8k16.row.col.f32.f16.f16.f32 "
                 "{%0,%1,%2,%3}, {%4,%5,%6,%7}, {%8,%9}, {%0,%1,%2,%3};"
                 : "+f"(d[0]), "+f"(d[1]), "+f"(d[2]), "+f"(d[3])
                 : "r"(a[0]), "r"(a[1]), "r"(a[2]), "r"(a[3]), "r"(b0), "r"(b1));
}
#define CP_ASYNC16(dst, src) \
    asm volatile("cp.async.cg.shared.global [%0], [%1], 16;" :: "r"(dst), "l"(src))
#define CP_COMMIT() asm volatile("cp.async.commit_group;")
#define CP_WAIT1()  asm volatile("cp.async.wait_group 1;")

// ======================= fp16 NT GEMM via mma.sync ==========================
// C[M,N] = A[M,K] @ B[N,K]^T (fp16 operands, fp32 accumulate), batched via z.
// Tile 128x128xKC, 3-stage cp.async, 8 warps (2M x 4N), warp tile 64x32.
// KC = 32 (pitch 80 B) or 64 (pitch 144 B); both ldmatrix conflict-free.
// EPI: 0 = +bias -> outF[m*N+n]
//      1 = relu(+bias) -> fp16 outH[m*N+n]
//      4 = scores: p = mask ? 0 : exp(acc*scale) -> fp16 outH; col partials -> csP
//      7 = fused QKV: seg=n/768 -> 0: q scatter fp16, 1: k scatter fp16,
//          2: v scatter fp32 [b,h,d,s]; all +bias[n]
template<int EPI, int KC>
__global__ void __launch_bounds__(256, 2)
gemm_mma(const __half* __restrict__ A, const __half* __restrict__ Bw,
         int N, int Kp, long strideA, long strideB,
         const float* __restrict__ bias, const uint32_t* __restrict__ mb, float scale,
         float* __restrict__ outF, __half* __restrict__ outH,
         float* __restrict__ csP)
{
    constexpr int PITCH = (KC == 32) ? 80 : 144;          // bytes per smem row
    constexpr int STG   = 128 * PITCH;                    // one matrix, one stage

    extern __shared__ char dynsm[];
    __shared__ float cs_sm[128];

    const int z = blockIdx.z;
    A  += (size_t)z * strideA;
    Bw += (size_t)z * strideB;

    const int tid  = threadIdx.x;
    const int wid  = tid >> 5;
    const int lane = tid & 31;
    const int m0   = blockIdx.y * 128;
    const int n0   = blockIdx.x * 128;
    const int wm   = (wid & 1) * 64;
    const int wn   = (wid >> 1) * 32;

    const uint32_t smBase = smem_u32(dynsm);

    float acc[4][4][4];
    #pragma unroll
    for (int i = 0; i < 4; ++i)
        #pragma unroll
        for (int j = 0; j < 4; ++j)
            #pragma unroll
            for (int p = 0; p < 4; ++p) acc[i][j][p] = 0.f;

    const int nk = Kp / KC;

    auto stage = [&](int s, int kt) {
        const int kc = kt * KC;
        const uint32_t base = smBase + s * (2 * STG);
        #pragma unroll
        for (int i = 0; i < KC / 16; ++i) {
            const int id = tid + i * 256;
            const int r  = id / (KC / 8);
            const int c  = (id % (KC / 8)) * 8;
            const uint32_t dA = base + (uint32_t)(r * PITCH + c * 2);
            const uint32_t dB = dA + STG;
            CP_ASYNC16(dA, &A [(size_t)(m0 + r) * Kp + kc + c]);
            CP_ASYNC16(dB, &Bw[(size_t)(n0 + r) * Kp + kc + c]);
        }
    };

    stage(0, 0); CP_COMMIT();
    stage(1, 1); CP_COMMIT();

    const int lrow = lane & 15;
    const int lcol = (lane >> 4) * 8;

    for (int kt = 0; kt < nk; ++kt) {
        CP_WAIT1();
        __syncthreads();

        const uint32_t aBase = smBase + (kt % 3) * (2 * STG);
        const uint32_t bBase = aBase + STG;

        #pragma unroll
        for (int ks = 0; ks < KC; ks += 16) {
            uint32_t a[4][4];
            #pragma unroll
            for (int mi = 0; mi < 4; ++mi) {
                const uint32_t ad = aBase + (uint32_t)(wm + mi * 16 + lrow) * PITCH
                                          + (uint32_t)(ks + lcol) * 2;
                ldsm_x4(a[mi][0], a[mi][1], a[mi][2], a[mi][3], ad);
            }
            uint32_t b[2][4];
            #pragma unroll
            for (int bj = 0; bj < 2; ++bj) {
                const uint32_t bd = bBase + (uint32_t)(wn + bj * 16 + lrow) * PITCH
                                          + (uint32_t)(ks + lcol) * 2;
                ldsm_x4(b[bj][0], b[bj][1], b[bj][2], b[bj][3], bd);
            }
            #pragma unroll
            for (int mi = 0; mi < 4; ++mi)
                #pragma unroll
                for (int nj = 0; nj < 4; ++nj)
                    mma16816h(acc[mi][nj], a[mi], b[nj >> 1][nj & 1], b[nj >> 1][(nj & 1) + 2]);
        }

        if (kt + 2 < nk) stage((kt + 2) % 3, kt + 2);
        CP_COMMIT();
    }

    // ---------------- epilogue ----------------
    const int r4 = lane >> 2;
    const int c2 = (lane & 3) * 2;

    float cs[4][2];
    #pragma unroll
    for (int nj = 0; nj < 4; ++nj) { cs[nj][0] = 0.f; cs[nj][1] = 0.f; }

    const int seg7 = n0 / Ec;   // EPI 7: 0=q, 1=k, 2=v (tiles never straddle)

    #pragma unroll
    for (int mi = 0; mi < 4; ++mi) {
        #pragma unroll
        for (int half = 0; half < 2; ++half) {
            const int m = m0 + wm + mi * 16 + r4 + half * 8;
            uint32_t word = 0;
            if (EPI == 4) {
                const int bq = z / Hc;
                word = mb[((size_t)bq * Sc + m) * (Sc / 32) + (size_t)(n0 + wn) / 32];
            }
            #pragma unroll
            for (int nj = 0; nj < 4; ++nj) {
                const int n = n0 + wn + nj * 8 + c2;
                float v0 = acc[mi][nj][half * 2];
                float v1 = acc[mi][nj][half * 2 + 1];
                if (EPI != 4) { v0 += bias[n]; v1 += bias[n + 1]; }
                if (EPI == 0) {
                    *reinterpret_cast<float2*>(&outF[(size_t)m * N + n]) = make_float2(v0, v1);
                } else if (EPI == 1) {
                    *reinterpret_cast<__half2*>(&outH[(size_t)m * N + n]) =
                        __floats2half2_rn(fmaxf(v0, 0.f), fmaxf(v1, 0.f));
                } else if (EPI == 4) {
                    const int bit0 = (word >> (n & 31)) & 1;
                    const int bit1 = (word >> ((n + 1) & 31)) & 1;
                    const float e0 = bit0 ? 0.f : __expf(v0 * scale);
                    const float e1 = bit1 ? 0.f : __expf(v1 * scale);
                    *reinterpret_cast<__half2*>(&outH[((size_t)z * Sc + m) * Sc + n]) =
                        __floats2half2_rn(e0, e1);
                    cs[nj][0] += e0; cs[nj][1] += e1;
                } else { // EPI 7: fused QKV
                    const int col = n - seg7 * Ec;
                    const int b = m >> 11, s = m & 2047;
                    const int h = col >> 6, d = col & 63;
                    if (seg7 < 2) {
                        *reinterpret_cast<__half2*>(
                            &outH[seg7 * QKH_STRIDE +
                                  (((size_t)b * Hc + h) * Sc + s) * DHc + d]) =
                            __floats2half2_rn(v0, v1);
                    } else {
                        outF[(((size_t)b * Hc + h) * DHc + d)     * Sc + s] = v0;
                        outF[(((size_t)b * Hc + h) * DHc + d + 1) * Sc + s] = v1;
                    }
                }
            }
        }
    }

    if (EPI == 4) {
        #pragma unroll
        for (int nj = 0; nj < 4; ++nj)
            #pragma unroll
            for (int p = 0; p < 2; ++p) {
                float v = cs[nj][p];
                v += __shfl_xor_sync(0xffffffffu, v, 4);
                v += __shfl_xor_sync(0xffffffffu, v, 8);
                v += __shfl_xor_sync(0xffffffffu, v, 16);
                cs[nj][p] = v;
            }
        if (tid < 128) cs_sm[tid] = 0.f;
        __syncthreads();
        if (r4 == 0) {
            #pragma unroll
            for (int nj = 0; nj < 4; ++nj) {
                atomicAdd(&cs_sm[wn + nj * 8 + c2],     cs[nj][0]);  // 2 adds/addr: commutative
                atomicAdd(&cs_sm[wn + nj * 8 + c2 + 1], cs[nj][1]);
            }
        }
        __syncthreads();
        if (tid < 128)
            csP[((size_t)z * 16 + blockIdx.y) * Sc + n0 + tid] = cs_sm[tid];
    }
}

#define GEMM_SMEM32 (3 * 2 * 128 * 80)    // 61440
#define GEMM_SMEM64 (3 * 2 * 128 * 144)   // 110592

// ======================= attn@V: plain fp16 NT GEMM =========================
#define AV_A_BYTES (128 * 40 * 2)   // 10240
#define AV_B_BYTES (64 * 40 * 2)    // 5120

__global__ void __launch_bounds__(256, 2)
gemm_av_h(const __half* __restrict__ P, const __half* __restrict__ VH,
          float* __restrict__ out)
{
    __shared__ __half sm[3 * (128 + 64) * 40];

    const int z = blockIdx.z;
    const __half* A  = P  + (size_t)z * Sc * Sc;
    const __half* Bm = VH + (size_t)z * DHc * Sc;

    const int tid  = threadIdx.x;
    const int wid  = tid >> 5;
    const int lane = tid & 31;
    const int m0   = blockIdx.y * 128;
    const int wm   = (wid & 1) * 64;
    const int wn   = (wid >> 1) * 16;

    const uint32_t smBase = smem_u32(sm);

    float acc[4][2][4];
    #pragma unroll
    for (int i = 0; i < 4; ++i)
        #pragma unroll
        for (int j = 0; j < 2; ++j)
            #pragma unroll
            for (int p = 0; p < 4; ++p) acc[i][j][p] = 0.f;

    const int nk = Sc / 32;   // 64

    auto stage = [&](int s, int kt) {
        const int kc = kt * 32;
        const uint32_t base = smBase + s * (AV_A_BYTES + AV_B_BYTES);
        #pragma unroll
        for (int i = 0; i < 3; ++i) {
            const int id = tid + i * 256;
            if (id < 512) {
                const int r = id >> 2, c = (id & 3) * 8;
                CP_ASYNC16(base + (uint32_t)(r * 80 + c * 2),
                           &A[(size_t)(m0 + r) * Sc + kc + c]);
            } else {
                const int id2 = id - 512;
                const int r = id2 >> 2, c = (id2 & 3) * 8;
                CP_ASYNC16(base + AV_A_BYTES + (uint32_t)(r * 80 + c * 2),
                           &Bm[(size_t)r * Sc + kc + c]);
            }
        }
    };

    stage(0, 0); CP_COMMIT();
    stage(1, 1); CP_COMMIT();

    const int lrow = lane & 15;
    const int lcol = (lane >> 4) * 8;

    for (int kt = 0; kt < nk; ++kt) {
        CP_WAIT1();
        __syncthreads();

        const uint32_t aBase = smBase + (kt % 3) * (AV_A_BYTES + AV_B_BYTES);
        const uint32_t bBase = aBase + AV_A_BYTES;

        #pragma unroll
        for (int ks = 0; ks < 32; ks += 16) {
            uint32_t a[4][4];
            #pragma unroll
            for (int mi = 0; mi < 4; ++mi) {
                const uint32_t ad = aBase + (uint32_t)(wm + mi * 16 + lrow) * 80
                                          + (uint32_t)(ks + lcol) * 2;
                ldsm_x4(a[mi][0], a[mi][1], a[mi][2], a[mi][3], ad);
            }
            uint32_t b[4];
            const uint32_t bd = bBase + (uint32_t)(wn + lrow) * 80
                                      + (uint32_t)(ks + lcol) * 2;
            ldsm_x4(b[0], b[1], b[2], b[3], bd);
            #pragma unroll
            for (int mi = 0; mi < 4; ++mi)
                #pragma unroll
                for (int nj = 0; nj < 2; ++nj)
                    mma16816h(acc[mi][nj], a[mi], b[nj], b[nj + 2]);
        }

        if (kt + 2 < nk) stage((kt + 2) % 3, kt + 2);
        CP_COMMIT();
    }

    const int b = z / Hc, h = z % Hc;
    const int r4 = lane >> 2;
    const int c2 = (lane & 3) * 2;
    #pragma unroll
    for (int mi = 0; mi < 4; ++mi) {
        #pragma unroll
        for (int half = 0; half < 2; ++half) {
            const int s = m0 + wm + mi * 16 + r4 + half * 8;
            #pragma unroll
            for (int nj = 0; nj < 2; ++nj) {
                const int d = wn + nj * 8 + c2;
                float2 v = make_float2(acc[mi][nj][half * 2], acc[mi][nj][half * 2 + 1]);
                *reinterpret_cast<float2*>(&out[((size_t)b * Sc + s) * Dc + h * DHc + d]) = v;
            }
        }
    }
}

// ======================= small kernels ======================================
__global__ void cvt_h(const float* __restrict__ src, __half* __restrict__ dst)
{
    const size_t i = ((size_t)blockIdx.x * 256 + threadIdx.x) * 2;
    const float2 v = *reinterpret_cast<const float2*>(&src[i]);
    *reinterpret_cast<__half2*>(&dst[i]) = __floats2half2_rn(v.x, v.y);
}

__global__ void maskpack_kernel(const int* __restrict__ mask, uint32_t* __restrict__ mb)
{
    const size_t w = (size_t)blockIdx.x * 256 + threadIdx.x;
    const int4* p = reinterpret_cast<const int4*>(mask + w * 32);
    uint32_t bits = 0;
    #pragma unroll
    for (int i = 0; i < 8; ++i) {
        const int4 v = p[i];
        bits |= (v.x ? 1u : 0u) << (i * 4);
        bits |= (v.y ? 1u : 0u) << (i * 4 + 1);
        bits |= (v.z ? 1u : 0u) << (i * 4 + 2);
        bits |= (v.w ? 1u : 0u) << (i * 4 + 3);
    }
    mb[w] = bits;
}

__global__ void colsum_kernel(const float* __restrict__ csp, float* __restrict__ colsum)
{
    const size_t i = (size_t)blockIdx.x * 256 + threadIdx.x;   // z*Sc + t
    const size_t z = i >> 11;
    const int    t = (int)(i & 2047);
    float s = 0.f;
    #pragma unroll
    for (int my = 0; my < 16; ++my)
        s += csp[(z * 16 + my) * Sc + t];
    colsum[i] = s;
}

__global__ void vh_kernel(const float* __restrict__ vt, const float* __restrict__ colsum,
                          __half* __restrict__ vh)
{
    const size_t i = ((size_t)blockIdx.x * 256 + threadIdx.x) * 2;
    const size_t zd = i >> 11;
    const int    t  = (int)(i & 2047);
    const size_t z  = zd >> 6;
    const float2 v = *reinterpret_cast<const float2*>(&vt[i]);
    const float2 c = *reinterpret_cast<const float2*>(&colsum[z * Sc + t]);
    *reinterpret_cast<__half2*>(&vh[i]) =
        __floats2half2_rn(__fdividef(v.x, c.x), __fdividef(v.y, c.y));
}

// LN + residual. HOUT=0: fp32 out. HOUT=1: fp16 out.
template<int HOUT>
__global__ void ln_residual_kernel(const float* __restrict__ in,
                                   const float* __restrict__ gamma,
                                   const float* __restrict__ beta,
                                   float* __restrict__ out,
                                   __half* __restrict__ outH)
{
    const size_t row = blockIdx.x;
    const float* xr = in + row * Dc;
    const int tid = threadIdx.x;

    const float v0 = xr[tid], v1 = xr[tid + 256], v2 = xr[tid + 512];

    __shared__ float red[256];
    red[tid] = v0 + v1 + v2;
    __syncthreads();
    #pragma unroll
    for (int o = 128; o > 0; o >>= 1) {
        if (tid < o) red[tid] += red[tid + o];
        __syncthreads();
    }
    const float mu = red[0] * (1.f / Dc);
    __syncthreads();

    const float d0 = v0 - mu, d1 = v1 - mu, d2 = v2 - mu;
    red[tid] = d0 * d0 + d1 * d1 + d2 * d2;
    __syncthreads();
    #pragma unroll
    for (int o = 128; o > 0; o >>= 1) {
        if (tid < o) red[tid] += red[tid + o];
        __syncthreads();
    }
    const float rstd = rsqrtf(red[0] * (1.f / Dc) + 1e-5f);

    const float o0 = d0 * rstd * gamma[tid]       + beta[tid]       + v0;
    const float o1 = d1 * rstd * gamma[tid + 256] + beta[tid + 256] + v1;
    const float o2 = d2 * rstd * gamma[tid + 512] + beta[tid + 512] + v2;

    if (HOUT == 0) {
        float* orow = out + row * Dc;
        orow[tid] = o0; orow[tid + 256] = o1; orow[tid + 512] = o2;
    } else {
        __half* orow = outH + row * Dc;
        orow[tid]       = __float2half(o0);
        orow[tid + 256] = __float2half(o1);
        orow[tid + 512] = __float2half(o2);
    }
}

// ---------------------------------------------------------------------------
extern "C" void kernel_launch(void* const* d_in, const int* in_sizes, int n_in,
                              void* d_out, int out_size)
{
    (void)in_sizes; (void)n_in; (void)out_size;
    const float* x    = (const float*)d_in[0];
    const int*   mask = (const int*)d_in[1];
    const float* Wq = (const float*)d_in[2];
    const float* bq = (const float*)d_in[3];
    const float* Wk = (const float*)d_in[4];
    const float* bk = (const float*)d_in[5];
    const float* Wv = (const float*)d_in[6];
    const float* bv = (const float*)d_in[7];
    const float* gamma = (const float*)d_in[8];
    const float* beta  = (const float*)d_in[9];
    const float* W1 = (const float*)d_in[10];
    const float* b1 = (const float*)d_in[11];
    const float* W2 = (const float*)d_in[12];
    const float* b2 = (const float*)d_in[13];
    float* out = (float*)d_out;

    float *vt, *a, *bb, *csp, *colsum, *bqkv;
    __half *ph, *vh;
    uint32_t *mb;
    cudaGetSymbolAddress((void**)&vt,     g_vt);
    cudaGetSymbolAddress((void**)&a,      g_a);
    cudaGetSymbolAddress((void**)&bb,     g_b);
    cudaGetSymbolAddress((void**)&csp,    g_csp);
    cudaGetSymbolAddress((void**)&colsum, g_colsum);
    cudaGetSymbolAddress((void**)&ph,     g_ph);
    cudaGetSymbolAddress((void**)&vh,     g_vh);
    cudaGetSymbolAddress((void**)&mb,     g_mb);
    cudaGetSymbolAddress((void**)&bqkv,   g_bqkv);

    __half *xh, *ah, *hh, *qkh, *wqkv, *w1h, *w2h;
    cudaGetSymbolAddress((void**)&xh,   g_xh);
    cudaGetSymbolAddress((void**)&ah,   g_ah);
    cudaGetSymbolAddress((void**)&hh,   g_hh);
    cudaGetSymbolAddress((void**)&qkh,  g_qkh);
    cudaGetSymbolAddress((void**)&wqkv, g_wqkv);
    cudaGetSymbolAddress((void**)&w1h,  g_w1h);
    cudaGetSymbolAddress((void**)&w2h,  g_w2h);

    cudaFuncSetAttribute((const void*)gemm_mma<0,64>, cudaFuncAttributeMaxDynamicSharedMemorySize, GEMM_SMEM64);
    cudaFuncSetAttribute((const void*)gemm_mma<1,64>, cudaFuncAttributeMaxDynamicSharedMemorySize, GEMM_SMEM64);
    cudaFuncSetAttribute((const void*)gemm_mma<7,64>, cudaFuncAttributeMaxDynamicSharedMemorySize, GEMM_SMEM64);
    cudaFuncSetAttribute((const void*)gemm_mma<4,32>, cudaFuncAttributeMaxDynamicSharedMemorySize, GEMM_SMEM32);

    const int MS = Bc * Sc;               // 8192
    const float scale = 1.0f / sqrtf((float)Sc);

    // 0) mask bit-pack, fp16 conversions, combined bias (d2d copies)
    maskpack_kernel<<<(Bc * Sc * (Sc / 32)) / 256, 256>>>(mask, mb);
    cvt_h<<<(MS * Ec) / 512, 256>>>(x,  xh);
    cvt_h<<<(Dc * Ec) / 512, 256>>>(Wq, wqkv);
    cvt_h<<<(Dc * Ec) / 512, 256>>>(Wk, wqkv + (size_t)Dc * Ec);
    cvt_h<<<(Dc * Ec) / 512, 256>>>(Wv, wqkv + (size_t)2 * Dc * Ec);
    cvt_h<<<(Fc * Dc) / 512, 256>>>(W1, w1h);
    cvt_h<<<(Dc * Fc) / 512, 256>>>(W2, w2h);
    cudaMemcpyAsync(bqkv,          bq, Dc * sizeof(float), cudaMemcpyDeviceToDevice);
    cudaMemcpyAsync(bqkv + Dc,     bk, Dc * sizeof(float), cudaMemcpyDeviceToDevice);
    cudaMemcpyAsync(bqkv + 2 * Dc, bv, Dc * sizeof(float), cudaMemcpyDeviceToDevice);

    // 1) fused QKV projection: one GEMM, N = 2304
    {
        dim3 grid(3 * Dc / 128, MS / 128);
        gemm_mma<7,64><<<grid, 256, GEMM_SMEM64>>>(xh, wqkv, 3 * Dc, Ec, 0, 0,
                                                   bqkv, nullptr, 0.f, vt, qkh, nullptr);
    }

    // 2) p = exp(masked scores) fp16 + per-tile column partial sums
    {
        dim3 grid(Sc / 128, Sc / 128, Bc * Hc);
        gemm_mma<4,32><<<grid, 256, GEMM_SMEM32>>>(qkh, qkh + QKH_STRIDE, Sc, DHc,
                                                   (long)Sc * DHc, (long)Sc * DHc,
                                                   nullptr, mb, scale, nullptr, ph, csp);
    }

    // 3) column sums + normalized V (fp16)
    colsum_kernel<<<(Bc * Hc * Sc) / 256, 256>>>(csp, colsum);
    vh_kernel<<<(Bc * Hc * DHc * Sc) / 512, 256>>>(vt, colsum, vh);

    // 4) o = p @ vh^T -> concat heads
    {
        dim3 grid(1, Sc / 128, Bc * Hc);
        gemm_av_h<<<grid, 256>>>(ph, vh, a);
    }

    // 5) a = LN(a) + a  -> fp16
    ln_residual_kernel<1><<<MS, 256>>>(a, gamma, beta, nullptr, ah);

    // 6) h = relu(a @ W1^T + b1) -> fp16
    {
        dim3 grid(Fc / 128, MS / 128);
        gemm_mma<1,64><<<grid, 256, GEMM_SMEM64>>>(ah, w1h, Fc, Dc, 0, 0, b1,
                                                   nullptr, 0.f, nullptr, hh, nullptr);
    }

    // 7) bb = h @ W2^T + b2
    {
        dim3 grid(Dc / 128, MS / 128);
        gemm_mma<0,64><<<grid, 256, GEMM_SMEM64>>>(hh, w2h, Dc, Fc, 0, 0, b2,
                                                   nullptr, 0.f, bb, nullptr, nullptr);
    }

    // 8) out = LN(bb) + bb
    ln_residual_kernel<0><<<MS, 256>>>(bb, gamma, beta, out, nullptr);
}

// round 14
// speedup vs baseline: 1.1262x; 1.0122x over previous
#include <cuda_runtime.h>
#include <cuda_bf16.h>
#include <cuda_fp16.h>
#include <math.h>
#include <stdint.h>

// Problem dims (fixed by the reference)
#define Bc  4
#define Sc  2048
#define Ec  768
#define Dc  768
#define Hc  12
#define DHc 64
#define Fc  3072

#define QKH_STRIDE ((size_t)Bc*Hc*Sc*DHc)

// ---------------- scratch (device globals: allocation-free) ----------------
__device__ float    g_vt[(size_t)Bc*Hc*DHc*Sc];       // [B,H,dh,S] fp32
__device__ __half   g_ph[(size_t)Bc*Hc*Sc*Sc];        // p = exp(masked score) fp16
__device__ __half   g_vh[(size_t)Bc*Hc*DHc*Sc];       // v / colsum, fp16
__device__ float    g_csp[(size_t)Bc*Hc*16*Sc];       // per-mtile column partial sums
__device__ float    g_colsum[(size_t)Bc*Hc*Sc];
__device__ uint32_t g_mb[(size_t)Bc*Sc*(Sc/32)];      // bit-packed mask
__device__ float    g_a [(size_t)Bc*Sc*Dc];
__device__ float    g_b [(size_t)Bc*Sc*Dc];

// fp16 operand buffers
__device__ __half g_xh  [(size_t)Bc*Sc*Ec];
__device__ __half g_ah  [(size_t)Bc*Sc*Dc];           // post-LN1 fp16
__device__ __half g_hh  [(size_t)Bc*Sc*Fc];           // hidden fp16
__device__ __half g_qkh [2*QKH_STRIDE];               // q then k
__device__ __half g_wqkv[(size_t)3*Dc*Ec];            // Wq;Wk;Wv combined
__device__ float  g_bqkv[3*Dc];                       // bq;bk;bv combined
__device__ __half g_w1h [(size_t)Fc*Dc];
__device__ __half g_w2h [(size_t)Dc*Fc];

// ======================= warp-MMA helpers ===================================
__device__ __forceinline__ uint32_t smem_u32(const void* p) {
    uint32_t a;
    asm("{ .reg .u64 t; cvta.to.shared.u64 t, %1; cvt.u32.u64 %0, t; }" : "=r"(a) : "l"(p));
    return a;
}
__device__ __forceinline__ void ldsm_x4(uint32_t& r0, uint32_t& r1, uint32_t& r2, uint32_t& r3,
                                        uint32_t addr) {
    asm volatile("ldmatrix.sync.aligned.m8n8.x4.shared.b16 {%0,%1,%2,%3}, [%4];"
                 : "=r"(r0), "=r"(r1), "=r"(r2), "=r"(r3) : "r"(addr));
}
__device__ __forceinline__ void mma16816h(float* d, const uint32_t* a, uint32_t b0, uint32_t b1) {
    asm volatile("mma.sync.aligned.m16n8k16.row.col.f32.f16.f16.f32 "
                 "{%0,%1,%2,%3}, {%4,%5,%6,%7}, {%8,%9}, {%0,%1,%2,%3};"
                 : "+f"(d[0]), "+f"(d[1]), "+f"(d[2]), "+f"(d[3])
                 : "r"(a[0]), "r"(a[1]), "r"(a[2]), "r"(a[3]), "r"(b0), "r"(b1));
}
#define CP_ASYNC16(dst, src) \
    asm volatile("cp.async.cg.shared.global [%0], [%1], 16;" :: "r"(dst), "l"(src))
#define CP_COMMIT() asm volatile("cp.async.commit_group;")
#define CP_WAIT1()  asm volatile("cp.async.wait_group 1;")

// ======================= fp16 NT GEMM via mma.sync ==========================
// C[M,N] = A[M,K] @ B[N,K]^T (fp16 operands, fp32 accumulate), batched via z.
// Tile 128x128xKC, 3-stage cp.async, 8 warps (2M x 4N), warp tile 64x32.
// EPI: 0 = +bias -> outF[m*N+n]
//      1 = relu(+bias) -> fp16 outH[m*N+n]
//      4 = scores: p = mask ? 0 : exp(acc*scale) -> fp16 outH; col partials -> csP
//      7 = fused QKV: seg=n/768 -> 0: q scatter fp16, 1: k scatter fp16,
//          2: v scatter fp32 [b,h,d,s]; all +bias[n]
template<int EPI, int KC>
__global__ void __launch_bounds__(256, 2)
gemm_mma(const __half* __restrict__ A, const __half* __restrict__ Bw,
         int N, int Kp, long strideA, long strideB,
         const float* __restrict__ bias, const uint32_t* __restrict__ mb, float scale,
         float* __restrict__ outF, __half* __restrict__ outH,
         float* __restrict__ csP)
{
    constexpr int PITCH = (KC == 32) ? 80 : 144;          // bytes per smem row
    constexpr int STG   = 128 * PITCH;                    // one matrix, one stage

    extern __shared__ char dynsm[];
    __shared__ float cs_sm[128];

    const int z = blockIdx.z;
    A  += (size_t)z * strideA;
    Bw += (size_t)z * strideB;

    const int tid  = threadIdx.x;
    const int wid  = tid >> 5;
    const int lane = tid & 31;
    const int m0   = blockIdx.y * 128;
    const int n0   = blockIdx.x * 128;
    const int wm   = (wid & 1) * 64;
    const int wn   = (wid >> 1) * 32;

    const uint32_t smBase = smem_u32(dynsm);

    float acc[4][4][4];
    #pragma unroll
    for (int i = 0; i < 4; ++i)
        #pragma unroll
        for (int j = 0; j < 4; ++j)
            #pragma unroll
            for (int p = 0; p < 4; ++p) acc[i][j][p] = 0.f;

    const int nk = Kp / KC;

    auto stage = [&](int s, int kt) {
        const int kc = kt * KC;
        const uint32_t base = smBase + s * (2 * STG);
        #pragma unroll
        for (int i = 0; i < KC / 16; ++i) {
            const int id = tid + i * 256;
            const int r  = id / (KC / 8);
            const int c  = (id % (KC / 8)) * 8;
            const uint32_t dA = base + (uint32_t)(r * PITCH + c * 2);
            const uint32_t dB = dA + STG;
            CP_ASYNC16(dA, &A [(size_t)(m0 + r) * Kp + kc + c]);
            CP_ASYNC16(dB, &Bw[(size_t)(n0 + r) * Kp + kc + c]);
        }
    };

    stage(0, 0); CP_COMMIT();
    stage(1, 1); CP_COMMIT();

    const int lrow = lane & 15;
    const int lcol = (lane >> 4) * 8;

    for (int kt = 0; kt < nk; ++kt) {
        CP_WAIT1();
        __syncthreads();

        const uint32_t aBase = smBase + (kt % 3) * (2 * STG);
        const uint32_t bBase = aBase + STG;

        #pragma unroll
        for (int ks = 0; ks < KC; ks += 16) {
            uint32_t a[4][4];
            #pragma unroll
            for (int mi = 0; mi < 4; ++mi) {
                const uint32_t ad = aBase + (uint32_t)(wm + mi * 16 + lrow) * PITCH
                                          + (uint32_t)(ks + lcol) * 2;
                ldsm_x4(a[mi][0], a[mi][1], a[mi][2], a[mi][3], ad);
            }
            uint32_t b[2][4];
            #pragma unroll
            for (int bj = 0; bj < 2; ++bj) {
                const uint32_t bd = bBase + (uint32_t)(wn + bj * 16 + lrow) * PITCH
                                          + (uint32_t)(ks + lcol) * 2;
                ldsm_x4(b[bj][0], b[bj][1], b[bj][2], b[bj][3], bd);
            }
            #pragma unroll
            for (int mi = 0; mi < 4; ++mi)
                #pragma unroll
                for (int nj = 0; nj < 4; ++nj)
                    mma16816h(acc[mi][nj], a[mi], b[nj >> 1][nj & 1], b[nj >> 1][(nj & 1) + 2]);
        }

        if (kt + 2 < nk) stage((kt + 2) % 3, kt + 2);
        CP_COMMIT();
    }

    // ---------------- epilogue ----------------
    const int r4 = lane >> 2;
    const int c2 = (lane & 3) * 2;

    float cs[4][2];
    #pragma unroll
    for (int nj = 0; nj < 4; ++nj) { cs[nj][0] = 0.f; cs[nj][1] = 0.f; }

    const int seg7 = n0 / Ec;   // EPI 7: 0=q, 1=k, 2=v (tiles never straddle)

    #pragma unroll
    for (int mi = 0; mi < 4; ++mi) {
        #pragma unroll
        for (int half = 0; half < 2; ++half) {
            const int m = m0 + wm + mi * 16 + r4 + half * 8;
            uint32_t word = 0;
            if (EPI == 4) {
                const int bq = z / Hc;
                word = mb[((size_t)bq * Sc + m) * (Sc / 32) + (size_t)(n0 + wn) / 32];
            }
            #pragma unroll
            for (int nj = 0; nj < 4; ++nj) {
                const int n = n0 + wn + nj * 8 + c2;
                float v0 = acc[mi][nj][half * 2];
                float v1 = acc[mi][nj][half * 2 + 1];
                if (EPI != 4) { v0 += bias[n]; v1 += bias[n + 1]; }
                if (EPI == 0) {
                    *reinterpret_cast<float2*>(&outF[(size_t)m * N + n]) = make_float2(v0, v1);
                } else if (EPI == 1) {
                    *reinterpret_cast<__half2*>(&outH[(size_t)m * N + n]) =
                        __floats2half2_rn(fmaxf(v0, 0.f), fmaxf(v1, 0.f));
                } else if (EPI == 4) {
                    const int bit0 = (word >> (n & 31)) & 1;
                    const int bit1 = (word >> ((n + 1) & 31)) & 1;
                    const float e0 = bit0 ? 0.f : __expf(v0 * scale);
                    const float e1 = bit1 ? 0.f : __expf(v1 * scale);
                    *reinterpret_cast<__half2*>(&outH[((size_t)z * Sc + m) * Sc + n]) =
                        __floats2half2_rn(e0, e1);
                    cs[nj][0] += e0; cs[nj][1] += e1;
                } else { // EPI 7: fused QKV
                    const int col = n - seg7 * Ec;
                    const int b = m >> 11, s = m & 2047;
                    const int h = col >> 6, d = col & 63;
                    if (seg7 < 2) {
                        *reinterpret_cast<__half2*>(
                            &outH[seg7 * QKH_STRIDE +
                                  (((size_t)b * Hc + h) * Sc + s) * DHc + d]) =
                            __floats2half2_rn(v0, v1);
                    } else {
                        outF[(((size_t)b * Hc + h) * DHc + d)     * Sc + s] = v0;
                        outF[(((size_t)b * Hc + h) * DHc + d + 1) * Sc + s] = v1;
                    }
                }
            }
        }
    }

    if (EPI == 4) {
        #pragma unroll
        for (int nj = 0; nj < 4; ++nj)
            #pragma unroll
            for (int p = 0; p < 2; ++p) {
                float v = cs[nj][p];
                v += __shfl_xor_sync(0xffffffffu, v, 4);
                v += __shfl_xor_sync(0xffffffffu, v, 8);
                v += __shfl_xor_sync(0xffffffffu, v, 16);
                cs[nj][p] = v;
            }
        if (tid < 128) cs_sm[tid] = 0.f;
        __syncthreads();
        if (r4 == 0) {
            #pragma unroll
            for (int nj = 0; nj < 4; ++nj) {
                atomicAdd(&cs_sm[wn + nj * 8 + c2],     cs[nj][0]);  // 2 adds/addr: commutative
                atomicAdd(&cs_sm[wn + nj * 8 + c2 + 1], cs[nj][1]);
            }
        }
        __syncthreads();
        if (tid < 128)
            csP[((size_t)z * 16 + blockIdx.y) * Sc + n0 + tid] = cs_sm[tid];
    }
}

#define GEMM_SMEM32 (3 * 2 * 128 * 80)    // 61440
#define GEMM_SMEM64 (3 * 2 * 128 * 144)   // 110592

// ======================= attn@V: plain fp16 NT GEMM (KC=64) =================
#define AVP    144                         // bytes per smem row
#define AV_A_B (128 * AVP)                 // 18432
#define AV_B_B (64 * AVP)                  // 9216
#define AV_SMEM (3 * (AV_A_B + AV_B_B))    // 82944

__global__ void __launch_bounds__(256, 2)
gemm_av_h(const __half* __restrict__ P, const __half* __restrict__ VH,
          float* __restrict__ out)
{
    extern __shared__ char dynsm[];

    const int z = blockIdx.z;
    const __half* A  = P  + (size_t)z * Sc * Sc;
    const __half* Bm = VH + (size_t)z * DHc * Sc;

    const int tid  = threadIdx.x;
    const int wid  = tid >> 5;
    const int lane = tid & 31;
    const int m0   = blockIdx.y * 128;
    const int wm   = (wid & 1) * 64;
    const int wn   = (wid >> 1) * 16;

    const uint32_t smBase = smem_u32(dynsm);

    float acc[4][2][4];
    #pragma unroll
    for (int i = 0; i < 4; ++i)
        #pragma unroll
        for (int j = 0; j < 2; ++j)
            #pragma unroll
            for (int p = 0; p < 4; ++p) acc[i][j][p] = 0.f;

    const int nk = Sc / 64;   // 32

    auto stage = [&](int s, int kt) {
        const int kc = kt * 64;
        const uint32_t base = smBase + s * (AV_A_B + AV_B_B);
        #pragma unroll
        for (int i = 0; i < 6; ++i) {
            const int id = tid + i * 256;          // 0..1535
            if (id < 1024) {
                const int r = id >> 3, c = (id & 7) * 8;
                CP_ASYNC16(base + (uint32_t)(r * AVP + c * 2),
                           &A[(size_t)(m0 + r) * Sc + kc + c]);
            } else {
                const int id2 = id - 1024;
                const int r = id2 >> 3, c = (id2 & 7) * 8;
                CP_ASYNC16(base + AV_A_B + (uint32_t)(r * AVP + c * 2),
                           &Bm[(size_t)r * Sc + kc + c]);
            }
        }
    };

    stage(0, 0); CP_COMMIT();
    stage(1, 1); CP_COMMIT();

    const int lrow = lane & 15;
    const int lcol = (lane >> 4) * 8;

    for (int kt = 0; kt < nk; ++kt) {
        CP_WAIT1();
        __syncthreads();

        const uint32_t aBase = smBase + (kt % 3) * (AV_A_B + AV_B_B);
        const uint32_t bBase = aBase + AV_A_B;

        #pragma unroll
        for (int ks = 0; ks < 64; ks += 16) {
            uint32_t a[4][4];
            #pragma unroll
            for (int mi = 0; mi < 4; ++mi) {
                const uint32_t ad = aBase + (uint32_t)(wm + mi * 16 + lrow) * AVP
                                          + (uint32_t)(ks + lcol) * 2;
                ldsm_x4(a[mi][0], a[mi][1], a[mi][2], a[mi][3], ad);
            }
            uint32_t b[4];
            const uint32_t bd = bBase + (uint32_t)(wn + lrow) * AVP
                                      + (uint32_t)(ks + lcol) * 2;
            ldsm_x4(b[0], b[1], b[2], b[3], bd);
            #pragma unroll
            for (int mi = 0; mi < 4; ++mi)
                #pragma unroll
                for (int nj = 0; nj < 2; ++nj)
                    mma16816h(acc[mi][nj], a[mi], b[nj], b[nj + 2]);
        }

        if (kt + 2 < nk) stage((kt + 2) % 3, kt + 2);
        CP_COMMIT();
    }

    const int b = z / Hc, h = z % Hc;
    const int r4 = lane >> 2;
    const int c2 = (lane & 3) * 2;
    #pragma unroll
    for (int mi = 0; mi < 4; ++mi) {
        #pragma unroll
        for (int half = 0; half < 2; ++half) {
            const int s = m0 + wm + mi * 16 + r4 + half * 8;
            #pragma unroll
            for (int nj = 0; nj < 2; ++nj) {
                const int d = wn + nj * 8 + c2;
                float2 v = make_float2(acc[mi][nj][half * 2], acc[mi][nj][half * 2 + 1]);
                *reinterpret_cast<float2*>(&out[((size_t)b * Sc + s) * Dc + h * DHc + d]) = v;
            }
        }
    }
}

// ======================= small kernels ======================================
__global__ void cvt_h(const float* __restrict__ src, __half* __restrict__ dst)
{
    const size_t i = ((size_t)blockIdx.x * 256 + threadIdx.x) * 2;
    const float2 v = *reinterpret_cast<const float2*>(&src[i]);
    *reinterpret_cast<__half2*>(&dst[i]) = __floats2half2_rn(v.x, v.y);
}

__global__ void maskpack_kernel(const int* __restrict__ mask, uint32_t* __restrict__ mb)
{
    const size_t w = (size_t)blockIdx.x * 256 + threadIdx.x;
    const int4* p = reinterpret_cast<const int4*>(mask + w * 32);
    uint32_t bits = 0;
    #pragma unroll
    for (int i = 0; i < 8; ++i) {
        const int4 v = p[i];
        bits |= (v.x ? 1u : 0u) << (i * 4);
        bits |= (v.y ? 1u : 0u) << (i * 4 + 1);
        bits |= (v.z ? 1u : 0u) << (i * 4 + 2);
        bits |= (v.w ? 1u : 0u) << (i * 4 + 3);
    }
    mb[w] = bits;
}

__global__ void colsum_kernel(const float* __restrict__ csp, float* __restrict__ colsum)
{
    const size_t i = (size_t)blockIdx.x * 256 + threadIdx.x;   // z*Sc + t
    const size_t z = i >> 11;
    const int    t = (int)(i & 2047);
    float s = 0.f;
    #pragma unroll
    for (int my = 0; my < 16; ++my)
        s += csp[(z * 16 + my) * Sc + t];
    colsum[i] = s;
}

__global__ void vh_kernel(const float* __restrict__ vt, const float* __restrict__ colsum,
                          __half* __restrict__ vh)
{
    const size_t i = ((size_t)blockIdx.x * 256 + threadIdx.x) * 2;
    const size_t zd = i >> 11;
    const int    t  = (int)(i & 2047);
    const size_t z  = zd >> 6;
    const float2 v = *reinterpret_cast<const float2*>(&vt[i]);
    const float2 c = *reinterpret_cast<const float2*>(&colsum[z * Sc + t]);
    *reinterpret_cast<__half2*>(&vh[i]) =
        __floats2half2_rn(__fdividef(v.x, c.x), __fdividef(v.y, c.y));
}

// LN + residual. HOUT=0: fp32 out. HOUT=1: fp16 out.
template<int HOUT>
__global__ void ln_residual_kernel(const float* __restrict__ in,
                                   const float* __restrict__ gamma,
                                   const float* __restrict__ beta,
                                   float* __restrict__ out,
                                   __half* __restrict__ outH)
{
    const size_t row = blockIdx.x;
    const float* xr = in + row * Dc;
    const int tid = threadIdx.x;

    const float v0 = xr[tid], v1 = xr[tid + 256], v2 = xr[tid + 512];

    __shared__ float red[256];
    red[tid] = v0 + v1 + v2;
    __syncthreads();
    #pragma unroll
    for (int o = 128; o > 0; o >>= 1) {
        if (tid < o) red[tid] += red[tid + o];
        __syncthreads();
    }
    const float mu = red[0] * (1.f / Dc);
    __syncthreads();

    const float d0 = v0 - mu, d1 = v1 - mu, d2 = v2 - mu;
    red[tid] = d0 * d0 + d1 * d1 + d2 * d2;
    __syncthreads();
    #pragma unroll
    for (int o = 128; o > 0; o >>= 1) {
        if (tid < o) red[tid] += red[tid + o];
        __syncthreads();
    }
    const float rstd = rsqrtf(red[0] * (1.f / Dc) + 1e-5f);

    const float o0 = d0 * rstd * gamma[tid]       + beta[tid]       + v0;
    const float o1 = d1 * rstd * gamma[tid + 256] + beta[tid + 256] + v1;
    const float o2 = d2 * rstd * gamma[tid + 512] + beta[tid + 512] + v2;

    if (HOUT == 0) {
        float* orow = out + row * Dc;
        orow[tid] = o0; orow[tid + 256] = o1; orow[tid + 512] = o2;
    } else {
        __half* orow = outH + row * Dc;
        orow[tid]       = __float2half(o0);
        orow[tid + 256] = __float2half(o1);
        orow[tid + 512] = __float2half(o2);
    }
}

// ---------------------------------------------------------------------------
extern "C" void kernel_launch(void* const* d_in, const int* in_sizes, int n_in,
                              void* d_out, int out_size)
{
    (void)in_sizes; (void)n_in; (void)out_size;
    const float* x    = (const float*)d_in[0];
    const int*   mask = (const int*)d_in[1];
    const float* Wq = (const float*)d_in[2];
    const float* bq = (const float*)d_in[3];
    const float* Wk = (const float*)d_in[4];
    const float* bk = (const float*)d_in[5];
    const float* Wv = (const float*)d_in[6];
    const float* bv = (const float*)d_in[7];
    const float* gamma = (const float*)d_in[8];
    const float* beta  = (const float*)d_in[9];
    const float* W1 = (const float*)d_in[10];
    const float* b1 = (const float*)d_in[11];
    const float* W2 = (const float*)d_in[12];
    const float* b2 = (const float*)d_in[13];
    float* out = (float*)d_out;

    float *vt, *a, *bb, *csp, *colsum, *bqkv;
    __half *ph, *vh;
    uint32_t *mb;
    cudaGetSymbolAddress((void**)&vt,     g_vt);
    cudaGetSymbolAddress((void**)&a,      g_a);
    cudaGetSymbolAddress((void**)&bb,     g_b);
    cudaGetSymbolAddress((void**)&csp,    g_csp);
    cudaGetSymbolAddress((void**)&colsum, g_colsum);
    cudaGetSymbolAddress((void**)&ph,     g_ph);
    cudaGetSymbolAddress((void**)&vh,     g_vh);
    cudaGetSymbolAddress((void**)&mb,     g_mb);
    cudaGetSymbolAddress((void**)&bqkv,   g_bqkv);

    __half *xh, *ah, *hh, *qkh, *wqkv, *w1h, *w2h;
    cudaGetSymbolAddress((void**)&xh,   g_xh);
    cudaGetSymbolAddress((void**)&ah,   g_ah);
    cudaGetSymbolAddress((void**)&hh,   g_hh);
    cudaGetSymbolAddress((void**)&qkh,  g_qkh);
    cudaGetSymbolAddress((void**)&wqkv, g_wqkv);
    cudaGetSymbolAddress((void**)&w1h,  g_w1h);
    cudaGetSymbolAddress((void**)&w2h,  g_w2h);

    cudaFuncSetAttribute((const void*)gemm_mma<0,64>, cudaFuncAttributeMaxDynamicSharedMemorySize, GEMM_SMEM64);
    cudaFuncSetAttribute((const void*)gemm_mma<1,64>, cudaFuncAttributeMaxDynamicSharedMemorySize, GEMM_SMEM64);
    cudaFuncSetAttribute((const void*)gemm_mma<7,64>, cudaFuncAttributeMaxDynamicSharedMemorySize, GEMM_SMEM64);
    cudaFuncSetAttribute((const void*)gemm_mma<4,32>, cudaFuncAttributeMaxDynamicSharedMemorySize, GEMM_SMEM32);
    cudaFuncSetAttribute((const void*)gemm_av_h,      cudaFuncAttributeMaxDynamicSharedMemorySize, AV_SMEM);

    const int MS = Bc * Sc;               // 8192
    const float scale = 1.0f / sqrtf((float)Sc);

    // 0) mask bit-pack, fp16 conversions, combined bias (d2d copies)
    maskpack_kernel<<<(Bc * Sc * (Sc / 32)) / 256, 256>>>(mask, mb);
    cvt_h<<<(MS * Ec) / 512, 256>>>(x,  xh);
    cvt_h<<<(Dc * Ec) / 512, 256>>>(Wq, wqkv);
    cvt_h<<<(Dc * Ec) / 512, 256>>>(Wk, wqkv + (size_t)Dc * Ec);
    cvt_h<<<(Dc * Ec) / 512, 256>>>(Wv, wqkv + (size_t)2 * Dc * Ec);
    cvt_h<<<(Fc * Dc) / 512, 256>>>(W1, w1h);
    cvt_h<<<(Dc * Fc) / 512, 256>>>(W2, w2h);
    cudaMemcpyAsync(bqkv,          bq, Dc * sizeof(float), cudaMemcpyDeviceToDevice);
    cudaMemcpyAsync(bqkv + Dc,     bk, Dc * sizeof(float), cudaMemcpyDeviceToDevice);
    cudaMemcpyAsync(bqkv + 2 * Dc, bv, Dc * sizeof(float), cudaMemcpyDeviceToDevice);

    // 1) fused QKV projection: one GEMM, N = 2304
    {
        dim3 grid(3 * Dc / 128, MS / 128);
        gemm_mma<7,64><<<grid, 256, GEMM_SMEM64>>>(xh, wqkv, 3 * Dc, Ec, 0, 0,
                                                   bqkv, nullptr, 0.f, vt, qkh, nullptr);
    }

    // 2) p = exp(masked scores) fp16 + per-tile column partial sums
    {
        dim3 grid(Sc / 128, Sc / 128, Bc * Hc);
        gemm_mma<4,32><<<grid, 256, GEMM_SMEM32>>>(qkh, qkh + QKH_STRIDE, Sc, DHc,
                                                   (long)Sc * DHc, (long)Sc * DHc,
                                                   nullptr, mb, scale, nullptr, ph, csp);
    }

    // 3) column sums + normalized V (fp16)
    colsum_kernel<<<(Bc * Hc * Sc) / 256, 256>>>(csp, colsum);
    vh_kernel<<<(Bc * Hc * DHc * Sc) / 512, 256>>>(vt, colsum, vh);

    // 4) o = p @ vh^T -> concat heads (KC=64)
    {
        dim3 grid(1, Sc / 128, Bc * Hc);
        gemm_av_h<<<grid, 256, AV_SMEM>>>(ph, vh, a);
    }

    // 5) a = LN(a) + a  -> fp16
    ln_residual_kernel<1><<<MS, 256>>>(a, gamma, beta, nullptr, ah);

    // 6) h = relu(a @ W1^T + b1) -> fp16
    {
        dim3 grid(Fc / 128, MS / 128);
        gemm_mma<1,64><<<grid, 256, GEMM_SMEM64>>>(ah, w1h, Fc, Dc, 0, 0, b1,
                                                   nullptr, 0.f, nullptr, hh, nullptr);
    }

    // 7) bb = h @ W2^T + b2
    {
        dim3 grid(Dc / 128, MS / 128);
        gemm_mma<0,64><<<grid, 256, GEMM_SMEM64>>>(hh, w2h, Dc, Fc, 0, 0, b2,
                                                   nullptr, 0.f, bb, nullptr, nullptr);
    }

    // 8) out = LN(bb) + bb
    ln_residual_kernel<0><<<MS, 256>>>(bb, gamma, beta, out, nullptr);
}

// round 15
// speedup vs baseline: 1.1365x; 1.0092x over previous
#include <cuda_runtime.h>
#include <cuda_bf16.h>
#include <cuda_fp16.h>
#include <math.h>
#include <stdint.h>

// Problem dims (fixed by the reference)
#define Bc  4
#define Sc  2048
#define Ec  768
#define Dc  768
#define Hc  12
#define DHc 64
#define Fc  3072

#define QKH_STRIDE ((size_t)Bc*Hc*Sc*DHc)

// ---------------- scratch (device globals: allocation-free) ----------------
__device__ float    g_vt[(size_t)Bc*Hc*DHc*Sc];       // [B,H,dh,S] fp32
__device__ __half   g_ph[(size_t)Bc*Hc*Sc*Sc];        // p = exp(masked score) fp16
__device__ __half   g_vh[(size_t)Bc*Hc*DHc*Sc];       // v / colsum, fp16
__device__ float    g_csp[(size_t)Bc*Hc*16*Sc];       // per-mtile column partial sums
__device__ uint32_t g_mb[(size_t)Bc*Sc*(Sc/32)];      // bit-packed mask
__device__ float    g_a [(size_t)Bc*Sc*Dc];
__device__ float    g_b [(size_t)Bc*Sc*Dc];

// fp16 operand buffers
__device__ __half g_xh  [(size_t)Bc*Sc*Ec];
__device__ __half g_ah  [(size_t)Bc*Sc*Dc];           // post-LN1 fp16
__device__ __half g_hh  [(size_t)Bc*Sc*Fc];           // hidden fp16
__device__ __half g_qkh [2*QKH_STRIDE];               // q then k
__device__ __half g_wqkv[(size_t)3*Dc*Ec];            // Wq;Wk;Wv combined
__device__ float  g_bqkv[3*Dc];                       // bq;bk;bv combined
__device__ __half g_w1h [(size_t)Fc*Dc];
__device__ __half g_w2h [(size_t)Dc*Fc];

// ======================= warp-MMA helpers ===================================
__device__ __forceinline__ uint32_t smem_u32(const void* p) {
    uint32_t a;
    asm("{ .reg .u64 t; cvta.to.shared.u64 t, %1; cvt.u32.u64 %0, t; }" : "=r"(a) : "l"(p));
    return a;
}
__device__ __forceinline__ void ldsm_x4(uint32_t& r0, uint32_t& r1, uint32_t& r2, uint32_t& r3,
                                        uint32_t addr) {
    asm volatile("ldmatrix.sync.aligned.m8n8.x4.shared.b16 {%0,%1,%2,%3}, [%4];"
                 : "=r"(r0), "=r"(r1), "=r"(r2), "=r"(r3) : "r"(addr));
}
__device__ __forceinline__ void mma16816h(float* d, const uint32_t* a, uint32_t b0, uint32_t b1) {
    asm volatile("mma.sync.aligned.m16n8k16.row.col.f32.f16.f16.f32 "
                 "{%0,%1,%2,%3}, {%4,%5,%6,%7}, {%8,%9}, {%0,%1,%2,%3};"
                 : "+f"(d[0]), "+f"(d[1]), "+f"(d[2]), "+f"(d[3])
                 : "r"(a[0]), "r"(a[1]), "r"(a[2]), "r"(a[3]), "r"(b0), "r"(b1));
}
#define CP_ASYNC16(dst, src) \
    asm volatile("cp.async.cg.shared.global [%0], [%1], 16;" :: "r"(dst), "l"(src))
#define CP_COMMIT() asm volatile("cp.async.commit_group;")
#define CP_WAIT1()  asm volatile("cp.async.wait_group 1;")

// ======================= fp16 NT GEMM via mma.sync ==========================
// C[M,N] = A[M,K] @ B[N,K]^T (fp16 operands, fp32 accumulate), batched via z.
// Tile 128x128xKC, 3-stage cp.async, 8 warps (2M x 4N), warp tile 64x32.
// EPI: 0 = +bias -> outF[m*N+n]
//      1 = relu(+bias) -> fp16 outH[m*N+n]
//      4 = scores: p = mask ? 0 : exp(acc*scale) -> fp16 outH; col partials -> csP
//      7 = fused QKV: seg=n/768 -> 0: q scatter fp16, 1: k scatter fp16,
//          2: v scatter fp32 [b,h,d,s]; all +bias[n]
template<int EPI, int KC>
__global__ void __launch_bounds__(256, 2)
gemm_mma(const __half* __restrict__ A, const __half* __restrict__ Bw,
         int N, int Kp, long strideA, long strideB,
         const float* __restrict__ bias, const uint32_t* __restrict__ mb, float scale,
         float* __restrict__ outF, __half* __restrict__ outH,
         float* __restrict__ csP)
{
    constexpr int PITCH = (KC == 32) ? 80 : 144;          // bytes per smem row
    constexpr int STG   = 128 * PITCH;                    // one matrix, one stage

    extern __shared__ char dynsm[];
    __shared__ float cs_sm[128];

    const int z = blockIdx.z;
    A  += (size_t)z * strideA;
    Bw += (size_t)z * strideB;

    const int tid  = threadIdx.x;
    const int wid  = tid >> 5;
    const int lane = tid & 31;
    const int m0   = blockIdx.y * 128;
    const int n0   = blockIdx.x * 128;
    const int wm   = (wid & 1) * 64;
    const int wn   = (wid >> 1) * 32;

    const uint32_t smBase = smem_u32(dynsm);

    float acc[4][4][4];
    #pragma unroll
    for (int i = 0; i < 4; ++i)
        #pragma unroll
        for (int j = 0; j < 4; ++j)
            #pragma unroll
            for (int p = 0; p < 4; ++p) acc[i][j][p] = 0.f;

    const int nk = Kp / KC;

    auto stage = [&](int s, int kt) {
        const int kc = kt * KC;
        const uint32_t base = smBase + s * (2 * STG);
        #pragma unroll
        for (int i = 0; i < KC / 16; ++i) {
            const int id = tid + i * 256;
            const int r  = id / (KC / 8);
            const int c  = (id % (KC / 8)) * 8;
            const uint32_t dA = base + (uint32_t)(r * PITCH + c * 2);
            const uint32_t dB = dA + STG;
            CP_ASYNC16(dA, &A [(size_t)(m0 + r) * Kp + kc + c]);
            CP_ASYNC16(dB, &Bw[(size_t)(n0 + r) * Kp + kc + c]);
        }
    };

    stage(0, 0); CP_COMMIT();
    stage(1, 1); CP_COMMIT();

    const int lrow = lane & 15;
    const int lcol = (lane >> 4) * 8;

    for (int kt = 0; kt < nk; ++kt) {
        CP_WAIT1();
        __syncthreads();

        const uint32_t aBase = smBase + (kt % 3) * (2 * STG);
        const uint32_t bBase = aBase + STG;

        #pragma unroll
        for (int ks = 0; ks < KC; ks += 16) {
            uint32_t a[4][4];
            #pragma unroll
            for (int mi = 0; mi < 4; ++mi) {
                const uint32_t ad = aBase + (uint32_t)(wm + mi * 16 + lrow) * PITCH
                                          + (uint32_t)(ks + lcol) * 2;
                ldsm_x4(a[mi][0], a[mi][1], a[mi][2], a[mi][3], ad);
            }
            uint32_t b[2][4];
            #pragma unroll
            for (int bj = 0; bj < 2; ++bj) {
                const uint32_t bd = bBase + (uint32_t)(wn + bj * 16 + lrow) * PITCH
                                          + (uint32_t)(ks + lcol) * 2;
                ldsm_x4(b[bj][0], b[bj][1], b[bj][2], b[bj][3], bd);
            }
            #pragma unroll
            for (int mi = 0; mi < 4; ++mi)
                #pragma unroll
                for (int nj = 0; nj < 4; ++nj)
                    mma16816h(acc[mi][nj], a[mi], b[nj >> 1][nj & 1], b[nj >> 1][(nj & 1) + 2]);
        }

        if (kt + 2 < nk) stage((kt + 2) % 3, kt + 2);
        CP_COMMIT();
    }

    // ---------------- epilogue ----------------
    const int r4 = lane >> 2;
    const int c2 = (lane & 3) * 2;

    float cs[4][2];
    #pragma unroll
    for (int nj = 0; nj < 4; ++nj) { cs[nj][0] = 0.f; cs[nj][1] = 0.f; }

    const int seg7 = n0 / Ec;   // EPI 7: 0=q, 1=k, 2=v (tiles never straddle)

    #pragma unroll
    for (int mi = 0; mi < 4; ++mi) {
        #pragma unroll
        for (int half = 0; half < 2; ++half) {
            const int m = m0 + wm + mi * 16 + r4 + half * 8;
            uint32_t word = 0;
            if (EPI == 4) {
                const int bq = z / Hc;
                word = mb[((size_t)bq * Sc + m) * (Sc / 32) + (size_t)(n0 + wn) / 32];
            }
            #pragma unroll
            for (int nj = 0; nj < 4; ++nj) {
                const int n = n0 + wn + nj * 8 + c2;
                float v0 = acc[mi][nj][half * 2];
                float v1 = acc[mi][nj][half * 2 + 1];
                if (EPI != 4) { v0 += bias[n]; v1 += bias[n + 1]; }
                if (EPI == 0) {
                    *reinterpret_cast<float2*>(&outF[(size_t)m * N + n]) = make_float2(v0, v1);
                } else if (EPI == 1) {
                    *reinterpret_cast<__half2*>(&outH[(size_t)m * N + n]) =
                        __floats2half2_rn(fmaxf(v0, 0.f), fmaxf(v1, 0.f));
                } else if (EPI == 4) {
                    const int bit0 = (word >> (n & 31)) & 1;
                    const int bit1 = (word >> ((n + 1) & 31)) & 1;
                    const float e0 = bit0 ? 0.f : __expf(v0 * scale);
                    const float e1 = bit1 ? 0.f : __expf(v1 * scale);
                    *reinterpret_cast<__half2*>(&outH[((size_t)z * Sc + m) * Sc + n]) =
                        __floats2half2_rn(e0, e1);
                    cs[nj][0] += e0; cs[nj][1] += e1;
                } else { // EPI 7: fused QKV
                    const int col = n - seg7 * Ec;
                    const int b = m >> 11, s = m & 2047;
                    const int h = col >> 6, d = col & 63;
                    if (seg7 < 2) {
                        *reinterpret_cast<__half2*>(
                            &outH[seg7 * QKH_STRIDE +
                                  (((size_t)b * Hc + h) * Sc + s) * DHc + d]) =
                            __floats2half2_rn(v0, v1);
                    } else {
                        outF[(((size_t)b * Hc + h) * DHc + d)     * Sc + s] = v0;
                        outF[(((size_t)b * Hc + h) * DHc + d + 1) * Sc + s] = v1;
                    }
                }
            }
        }
    }

    if (EPI == 4) {
        #pragma unroll
        for (int nj = 0; nj < 4; ++nj)
            #pragma unroll
            for (int p = 0; p < 2; ++p) {
                float v = cs[nj][p];
                v += __shfl_xor_sync(0xffffffffu, v, 4);
                v += __shfl_xor_sync(0xffffffffu, v, 8);
                v += __shfl_xor_sync(0xffffffffu, v, 16);
                cs[nj][p] = v;
            }
        if (tid < 128) cs_sm[tid] = 0.f;
        __syncthreads();
        if (r4 == 0) {
            #pragma unroll
            for (int nj = 0; nj < 4; ++nj) {
                atomicAdd(&cs_sm[wn + nj * 8 + c2],     cs[nj][0]);  // 2 adds/addr: commutative
                atomicAdd(&cs_sm[wn + nj * 8 + c2 + 1], cs[nj][1]);
            }
        }
        __syncthreads();
        if (tid < 128)
            csP[((size_t)z * 16 + blockIdx.y) * Sc + n0 + tid] = cs_sm[tid];
    }
}

#define GEMM_SMEM32 (3 * 2 * 128 * 80)    // 61440
#define GEMM_SMEM64 (3 * 2 * 128 * 144)   // 110592

// ======================= attn@V: plain fp16 NT GEMM (KC=64) =================
#define AVP    144                         // bytes per smem row
#define AV_A_B (128 * AVP)                 // 18432
#define AV_B_B (64 * AVP)                  // 9216
#define AV_SMEM (3 * (AV_A_B + AV_B_B))    // 82944

__global__ void __launch_bounds__(256, 2)
gemm_av_h(const __half* __restrict__ P, const __half* __restrict__ VH,
          float* __restrict__ out)
{
    extern __shared__ char dynsm[];

    const int z = blockIdx.z;
    const __half* A  = P  + (size_t)z * Sc * Sc;
    const __half* Bm = VH + (size_t)z * DHc * Sc;

    const int tid  = threadIdx.x;
    const int wid  = tid >> 5;
    const int lane = tid & 31;
    const int m0   = blockIdx.y * 128;
    const int wm   = (wid & 1) * 64;
    const int wn   = (wid >> 1) * 16;

    const uint32_t smBase = smem_u32(dynsm);

    float acc[4][2][4];
    #pragma unroll
    for (int i = 0; i < 4; ++i)
        #pragma unroll
        for (int j = 0; j < 2; ++j)
            #pragma unroll
            for (int p = 0; p < 4; ++p) acc[i][j][p] = 0.f;

    const int nk = Sc / 64;   // 32

    auto stage = [&](int s, int kt) {
        const int kc = kt * 64;
        const uint32_t base = smBase + s * (AV_A_B + AV_B_B);
        #pragma unroll
        for (int i = 0; i < 6; ++i) {
            const int id = tid + i * 256;          // 0..1535
            if (id < 1024) {
                const int r = id >> 3, c = (id & 7) * 8;
                CP_ASYNC16(base + (uint32_t)(r * AVP + c * 2),
                           &A[(size_t)(m0 + r) * Sc + kc + c]);
            } else {
                const int id2 = id - 1024;
                const int r = id2 >> 3, c = (id2 & 7) * 8;
                CP_ASYNC16(base + AV_A_B + (uint32_t)(r * AVP + c * 2),
                           &Bm[(size_t)r * Sc + kc + c]);
            }
        }
    };

    stage(0, 0); CP_COMMIT();
    stage(1, 1); CP_COMMIT();

    const int lrow = lane & 15;
    const int lcol = (lane >> 4) * 8;

    for (int kt = 0; kt < nk; ++kt) {
        CP_WAIT1();
        __syncthreads();

        const uint32_t aBase = smBase + (kt % 3) * (AV_A_B + AV_B_B);
        const uint32_t bBase = aBase + AV_A_B;

        #pragma unroll
        for (int ks = 0; ks < 64; ks += 16) {
            uint32_t a[4][4];
            #pragma unroll
            for (int mi = 0; mi < 4; ++mi) {
                const uint32_t ad = aBase + (uint32_t)(wm + mi * 16 + lrow) * AVP
                                          + (uint32_t)(ks + lcol) * 2;
                ldsm_x4(a[mi][0], a[mi][1], a[mi][2], a[mi][3], ad);
            }
            uint32_t b[4];
            const uint32_t bd = bBase + (uint32_t)(wn + lrow) * AVP
                                      + (uint32_t)(ks + lcol) * 2;
            ldsm_x4(b[0], b[1], b[2], b[3], bd);
            #pragma unroll
            for (int mi = 0; mi < 4; ++mi)
                #pragma unroll
                for (int nj = 0; nj < 2; ++nj)
                    mma16816h(acc[mi][nj], a[mi], b[nj], b[nj + 2]);
        }

        if (kt + 2 < nk) stage((kt + 2) % 3, kt + 2);
        CP_COMMIT();
    }

    const int b = z / Hc, h = z % Hc;
    const int r4 = lane >> 2;
    const int c2 = (lane & 3) * 2;
    #pragma unroll
    for (int mi = 0; mi < 4; ++mi) {
        #pragma unroll
        for (int half = 0; half < 2; ++half) {
            const int s = m0 + wm + mi * 16 + r4 + half * 8;
            #pragma unroll
            for (int nj = 0; nj < 2; ++nj) {
                const int d = wn + nj * 8 + c2;
                float2 v = make_float2(acc[mi][nj][half * 2], acc[mi][nj][half * 2 + 1]);
                *reinterpret_cast<float2*>(&out[((size_t)b * Sc + s) * Dc + h * DHc + d]) = v;
            }
        }
    }
}

// ======================= small kernels ======================================
// One prep kernel: all weight fp32->fp16 conversions + combined bias copy.
#define WQK_SZ ((size_t)Dc*Ec)            // 589824
#define W1_SZ  ((size_t)Fc*Dc)            // 2359296
#define PREP_T0 (3*WQK_SZ)                // 1769472
#define PREP_T1 (PREP_T0 + W1_SZ)         // 4128768
#define PREP_T2 (PREP_T1 + W1_SZ)         // 6488064
#define PREP_TOT (PREP_T2 + 3*Dc)         // + 2304 bias floats
#define PREP_BLOCKS ((PREP_TOT/2 + 255)/256)

__global__ void prep_kernel(const float* __restrict__ Wq, const float* __restrict__ Wk,
                            const float* __restrict__ Wv, const float* __restrict__ W1,
                            const float* __restrict__ W2,
                            const float* __restrict__ bq, const float* __restrict__ bk,
                            const float* __restrict__ bv,
                            __half* __restrict__ wqkv, __half* __restrict__ w1h,
                            __half* __restrict__ w2h, float* __restrict__ bqkv)
{
    const size_t i = ((size_t)blockIdx.x * 256 + threadIdx.x) * 2;
    if (i >= PREP_TOT) return;
    if (i < PREP_T0) {
        const float* src; size_t off;
        if (i < WQK_SZ)            { src = Wq; off = i; }
        else if (i < 2 * WQK_SZ)   { src = Wk; off = i - WQK_SZ; }
        else                       { src = Wv; off = i - 2 * WQK_SZ; }
        const float2 v = *reinterpret_cast<const float2*>(&src[off]);
        *reinterpret_cast<__half2*>(&wqkv[i]) = __floats2half2_rn(v.x, v.y);
    } else if (i < PREP_T1) {
        const size_t off = i - PREP_T0;
        const float2 v = *reinterpret_cast<const float2*>(&W1[off]);
        *reinterpret_cast<__half2*>(&w1h[off]) = __floats2half2_rn(v.x, v.y);
    } else if (i < PREP_T2) {
        const size_t off = i - PREP_T1;
        const float2 v = *reinterpret_cast<const float2*>(&W2[off]);
        *reinterpret_cast<__half2*>(&w2h[off]) = __floats2half2_rn(v.x, v.y);
    } else {
        const size_t off = i - PREP_T2;     // 0..2302, even
        const float* src; size_t o2;
        if (off < (size_t)Dc)          { src = bq; o2 = off; }
        else if (off < (size_t)2 * Dc) { src = bk; o2 = off - Dc; }
        else                           { src = bv; o2 = off - 2 * Dc; }
        const float2 v = *reinterpret_cast<const float2*>(&src[o2]);
        *reinterpret_cast<float2*>(&bqkv[off]) = v;
    }
}

__global__ void cvt_h(const float* __restrict__ src, __half* __restrict__ dst)
{
    const size_t i = ((size_t)blockIdx.x * 256 + threadIdx.x) * 2;
    const float2 v = *reinterpret_cast<const float2*>(&src[i]);
    *reinterpret_cast<__half2*>(&dst[i]) = __floats2half2_rn(v.x, v.y);
}

__global__ void maskpack_kernel(const int* __restrict__ mask, uint32_t* __restrict__ mb)
{
    const size_t w = (size_t)blockIdx.x * 256 + threadIdx.x;
    const int4* p = reinterpret_cast<const int4*>(mask + w * 32);
    uint32_t bits = 0;
    #pragma unroll
    for (int i = 0; i < 8; ++i) {
        const int4 v = p[i];
        bits |= (v.x ? 1u : 0u) << (i * 4);
        bits |= (v.y ? 1u : 0u) << (i * 4 + 1);
        bits |= (v.z ? 1u : 0u) << (i * 4 + 2);
        bits |= (v.w ? 1u : 0u) << (i * 4 + 3);
    }
    mb[w] = bits;
}

// Fused colsum + vh: one thread per (z, t); same sequential 16-partial sum,
// same per-element __fdividef as before (bit-identical).
__global__ void vh2_kernel(const float* __restrict__ vt, const float* __restrict__ csp,
                           __half* __restrict__ vh)
{
    const size_t i = (size_t)blockIdx.x * 256 + threadIdx.x;   // z*Sc + t
    const size_t z = i >> 11;
    const int    t = (int)(i & 2047);
    float s = 0.f;
    #pragma unroll
    for (int my = 0; my < 16; ++my)
        s += csp[(z * 16 + my) * Sc + t];
    #pragma unroll 4
    for (int d = 0; d < DHc; ++d) {
        const size_t idx = ((z * DHc + d) << 11) + t;
        vh[idx] = __float2half(__fdividef(vt[idx], s));
    }
}

// LN + residual. HOUT=0: fp32 out. HOUT=1: fp16 out.
template<int HOUT>
__global__ void ln_residual_kernel(const float* __restrict__ in,
                                   const float* __restrict__ gamma,
                                   const float* __restrict__ beta,
                                   float* __restrict__ out,
                                   __half* __restrict__ outH)
{
    const size_t row = blockIdx.x;
    const float* xr = in + row * Dc;
    const int tid = threadIdx.x;

    const float v0 = xr[tid], v1 = xr[tid + 256], v2 = xr[tid + 512];

    __shared__ float red[256];
    red[tid] = v0 + v1 + v2;
    __syncthreads();
    #pragma unroll
    for (int o = 128; o > 0; o >>= 1) {
        if (tid < o) red[tid] += red[tid + o];
        __syncthreads();
    }
    const float mu = red[0] * (1.f / Dc);
    __syncthreads();

    const float d0 = v0 - mu, d1 = v1 - mu, d2 = v2 - mu;
    red[tid] = d0 * d0 + d1 * d1 + d2 * d2;
    __syncthreads();
    #pragma unroll
    for (int o = 128; o > 0; o >>= 1) {
        if (tid < o) red[tid] += red[tid + o];
        __syncthreads();
    }
    const float rstd = rsqrtf(red[0] * (1.f / Dc) + 1e-5f);

    const float o0 = d0 * rstd * gamma[tid]       + beta[tid]       + v0;
    const float o1 = d1 * rstd * gamma[tid + 256] + beta[tid + 256] + v1;
    const float o2 = d2 * rstd * gamma[tid + 512] + beta[tid + 512] + v2;

    if (HOUT == 0) {
        float* orow = out + row * Dc;
        orow[tid] = o0; orow[tid + 256] = o1; orow[tid + 512] = o2;
    } else {
        __half* orow = outH + row * Dc;
        orow[tid]       = __float2half(o0);
        orow[tid + 256] = __float2half(o1);
        orow[tid + 512] = __float2half(o2);
    }
}

// ---------------------------------------------------------------------------
extern "C" void kernel_launch(void* const* d_in, const int* in_sizes, int n_in,
                              void* d_out, int out_size)
{
    (void)in_sizes; (void)n_in; (void)out_size;
    const float* x    = (const float*)d_in[0];
    const int*   mask = (const int*)d_in[1];
    const float* Wq = (const float*)d_in[2];
    const float* bq = (const float*)d_in[3];
    const float* Wk = (const float*)d_in[4];
    const float* bk = (const float*)d_in[5];
    const float* Wv = (const float*)d_in[6];
    const float* bv = (const float*)d_in[7];
    const float* gamma = (const float*)d_in[8];
    const float* beta  = (const float*)d_in[9];
    const float* W1 = (const float*)d_in[10];
    const float* b1 = (const float*)d_in[11];
    const float* W2 = (const float*)d_in[12];
    const float* b2 = (const float*)d_in[13];
    float* out = (float*)d_out;

    float *vt, *a, *bb, *csp, *bqkv;
    __half *ph, *vh;
    uint32_t *mb;
    cudaGetSymbolAddress((void**)&vt,     g_vt);
    cudaGetSymbolAddress((void**)&a,      g_a);
    cudaGetSymbolAddress((void**)&bb,     g_b);
    cudaGetSymbolAddress((void**)&csp,    g_csp);
    cudaGetSymbolAddress((void**)&ph,     g_ph);
    cudaGetSymbolAddress((void**)&vh,     g_vh);
    cudaGetSymbolAddress((void**)&mb,     g_mb);
    cudaGetSymbolAddress((void**)&bqkv,   g_bqkv);

    __half *xh, *ah, *hh, *qkh, *wqkv, *w1h, *w2h;
    cudaGetSymbolAddress((void**)&xh,   g_xh);
    cudaGetSymbolAddress((void**)&ah,   g_ah);
    cudaGetSymbolAddress((void**)&hh,   g_hh);
    cudaGetSymbolAddress((void**)&qkh,  g_qkh);
    cudaGetSymbolAddress((void**)&wqkv, g_wqkv);
    cudaGetSymbolAddress((void**)&w1h,  g_w1h);
    cudaGetSymbolAddress((void**)&w2h,  g_w2h);

    cudaFuncSetAttribute((const void*)gemm_mma<0,64>, cudaFuncAttributeMaxDynamicSharedMemorySize, GEMM_SMEM64);
    cudaFuncSetAttribute((const void*)gemm_mma<1,64>, cudaFuncAttributeMaxDynamicSharedMemorySize, GEMM_SMEM64);
    cudaFuncSetAttribute((const void*)gemm_mma<7,64>, cudaFuncAttributeMaxDynamicSharedMemorySize, GEMM_SMEM64);
    cudaFuncSetAttribute((const void*)gemm_mma<4,32>, cudaFuncAttributeMaxDynamicSharedMemorySize, GEMM_SMEM32);
    cudaFuncSetAttribute((const void*)gemm_av_h,      cudaFuncAttributeMaxDynamicSharedMemorySize, AV_SMEM);

    const int MS = Bc * Sc;               // 8192
    const float scale = 1.0f / sqrtf((float)Sc);

    // 0) mask bit-pack + x conversion + all-weights prep (one kernel)
    maskpack_kernel<<<(Bc * Sc * (Sc / 32)) / 256, 256>>>(mask, mb);
    cvt_h<<<(MS * Ec) / 512, 256>>>(x, xh);
    prep_kernel<<<PREP_BLOCKS, 256>>>(Wq, Wk, Wv, W1, W2, bq, bk, bv,
                                      wqkv, w1h, w2h, bqkv);

    // 1) fused QKV projection: one GEMM, N = 2304
    {
        dim3 grid(3 * Dc / 128, MS / 128);
        gemm_mma<7,64><<<grid, 256, GEMM_SMEM64>>>(xh, wqkv, 3 * Dc, Ec, 0, 0,
                                                   bqkv, nullptr, 0.f, vt, qkh, nullptr);
    }

    // 2) p = exp(masked scores) fp16 + per-tile column partial sums
    {
        dim3 grid(Sc / 128, Sc / 128, Bc * Hc);
        gemm_mma<4,32><<<grid, 256, GEMM_SMEM32>>>(qkh, qkh + QKH_STRIDE, Sc, DHc,
                                                   (long)Sc * DHc, (long)Sc * DHc,
                                                   nullptr, mb, scale, nullptr, ph, csp);
    }

    // 3) fused column-sum + normalized V (fp16)
    vh2_kernel<<<(Bc * Hc * Sc) / 256, 256>>>(vt, csp, vh);

    // 4) o = p @ vh^T -> concat heads (KC=64)
    {
        dim3 grid(1, Sc / 128, Bc * Hc);
        gemm_av_h<<<grid, 256, AV_SMEM>>>(ph, vh, a);
    }

    // 5) a = LN(a) + a  -> fp16
    ln_residual_kernel<1><<<MS, 256>>>(a, gamma, beta, nullptr, ah);

    // 6) h = relu(a @ W1^T + b1) -> fp16
    {
        dim3 grid(Fc / 128, MS / 128);
        gemm_mma<1,64><<<grid, 256, GEMM_SMEM64>>>(ah, w1h, Fc, Dc, 0, 0, b1,
                                                   nullptr, 0.f, nullptr, hh, nullptr);
    }

    // 7) bb = h @ W2^T + b2
    {
        dim3 grid(Dc / 128, MS / 128);
        gemm_mma<0,64><<<grid, 256, GEMM_SMEM64>>>(hh, w2h, Dc, Fc, 0, 0, b2,
                                                   nullptr, 0.f, bb, nullptr, nullptr);
    }

    // 8) out = LN(bb) + bb
    ln_residual_kernel<0><<<MS, 256>>>(bb, gamma, beta, out, nullptr);
}

// round 16
// speedup vs baseline: 1.1756x; 1.0343x over previous
#include <cuda_runtime.h>
#include <cuda_bf16.h>
#include <cuda_fp16.h>
#include <math.h>
#include <stdint.h>

// Problem dims (fixed by the reference)
#define Bc  4
#define Sc  2048
#define Ec  768
#define Dc  768
#define Hc  12
#define DHc 64
#define Fc  3072

#define QKH_STRIDE ((size_t)Bc*Hc*Sc*DHc)

// ---------------- scratch (device globals: allocation-free) ----------------
__device__ float    g_vt[(size_t)Bc*Hc*DHc*Sc];       // [B,H,dh,S] fp32
__device__ __half   g_ph[(size_t)Bc*Hc*Sc*Sc];        // p = exp(masked score) fp16
__device__ __half   g_vh[(size_t)Bc*Hc*DHc*Sc];       // v / colsum, fp16
__device__ float    g_csp[(size_t)Bc*Hc*16*Sc];       // per-mtile column partial sums
__device__ uint32_t g_mb[(size_t)Bc*Sc*(Sc/32)];      // bit-packed mask
__device__ float    g_a [(size_t)Bc*Sc*Dc];
__device__ float    g_b [(size_t)Bc*Sc*Dc];

// fp16 operand buffers
__device__ __half g_xh  [(size_t)Bc*Sc*Ec];
__device__ __half g_ah  [(size_t)Bc*Sc*Dc];           // post-LN1 fp16
__device__ __half g_hh  [(size_t)Bc*Sc*Fc];           // hidden fp16
__device__ __half g_qkh [2*QKH_STRIDE];               // q then k
__device__ __half g_wqkv[(size_t)3*Dc*Ec];            // Wq;Wk;Wv combined
__device__ float  g_bqkv[3*Dc];                       // bq;bk;bv combined
__device__ __half g_w1h [(size_t)Fc*Dc];
__device__ __half g_w2h [(size_t)Dc*Fc];

// ======================= warp-MMA helpers ===================================
__device__ __forceinline__ uint32_t smem_u32(const void* p) {
    uint32_t a;
    asm("{ .reg .u64 t; cvta.to.shared.u64 t, %1; cvt.u32.u64 %0, t; }" : "=r"(a) : "l"(p));
    return a;
}
__device__ __forceinline__ void ldsm_x4(uint32_t& r0, uint32_t& r1, uint32_t& r2, uint32_t& r3,
                                        uint32_t addr) {
    asm volatile("ldmatrix.sync.aligned.m8n8.x4.shared.b16 {%0,%1,%2,%3}, [%4];"
                 : "=r"(r0), "=r"(r1), "=r"(r2), "=r"(r3) : "r"(addr));
}
__device__ __forceinline__ void mma16816h(float* d, const uint32_t* a, uint32_t b0, uint32_t b1) {
    asm volatile("mma.sync.aligned.m16n8k16.row.col.f32.f16.f16.f32 "
                 "{%0,%1,%2,%3}, {%4,%5,%6,%7}, {%8,%9}, {%0,%1,%2,%3};"
                 : "+f"(d[0]), "+f"(d[1]), "+f"(d[2]), "+f"(d[3])
                 : "r"(a[0]), "r"(a[1]), "r"(a[2]), "r"(a[3]), "r"(b0), "r"(b1));
}
#define CP_ASYNC16(dst, src) \
    asm volatile("cp.async.cg.shared.global [%0], [%1], 16;" :: "r"(dst), "l"(src))
#define CP_COMMIT() asm volatile("cp.async.commit_group;")
#define CP_WAIT1()  asm volatile("cp.async.wait_group 1;")

// ======================= fp16 NT GEMM via mma.sync ==========================
// C[M,N] = A[M,K] @ B[N,K]^T (fp16 operands, fp32 accumulate), batched via z.
// Tile 128x128xKC, 3-stage cp.async, 8 warps (2M x 4N), warp tile 64x32.
// EPI: 0 = +bias -> outF[m*N+n]
//      1 = relu(+bias) -> fp16 outH[m*N+n]
//      4 = scores: p = mask ? 0 : exp(acc*scale) -> fp16 outH (smem-staged,
//          coalesced); col partials -> csP
//      7 = fused QKV: seg=n/768 -> 0: q scatter fp16, 1: k scatter fp16,
//          2: v scatter fp32 [b,h,d,s]; all +bias[n]
#define STGP 272   // staging pitch (bytes) for EPI4 smem flush

template<int EPI, int KC>
__global__ void __launch_bounds__(256, 2)
gemm_mma(const __half* __restrict__ A, const __half* __restrict__ Bw,
         int N, int Kp, long strideA, long strideB,
         const float* __restrict__ bias, const uint32_t* __restrict__ mb, float scale,
         float* __restrict__ outF, __half* __restrict__ outH,
         float* __restrict__ csP)
{
    constexpr int PITCH = (KC == 32) ? 80 : 144;          // bytes per smem row
    constexpr int STG   = 128 * PITCH;                    // one matrix, one stage

    extern __shared__ char dynsm[];
    __shared__ float cs_sm[128];

    const int z = blockIdx.z;
    A  += (size_t)z * strideA;
    Bw += (size_t)z * strideB;

    const int tid  = threadIdx.x;
    const int wid  = tid >> 5;
    const int lane = tid & 31;
    const int m0   = blockIdx.y * 128;
    const int n0   = blockIdx.x * 128;
    const int wm   = (wid & 1) * 64;
    const int wn   = (wid >> 1) * 32;

    const uint32_t smBase = smem_u32(dynsm);

    float acc[4][4][4];
    #pragma unroll
    for (int i = 0; i < 4; ++i)
        #pragma unroll
        for (int j = 0; j < 4; ++j)
            #pragma unroll
            for (int p = 0; p < 4; ++p) acc[i][j][p] = 0.f;

    const int nk = Kp / KC;

    auto stage = [&](int s, int kt) {
        const int kc = kt * KC;
        const uint32_t base = smBase + s * (2 * STG);
        #pragma unroll
        for (int i = 0; i < KC / 16; ++i) {
            const int id = tid + i * 256;
            const int r  = id / (KC / 8);
            const int c  = (id % (KC / 8)) * 8;
            const uint32_t dA = base + (uint32_t)(r * PITCH + c * 2);
            const uint32_t dB = dA + STG;
            CP_ASYNC16(dA, &A [(size_t)(m0 + r) * Kp + kc + c]);
            CP_ASYNC16(dB, &Bw[(size_t)(n0 + r) * Kp + kc + c]);
        }
    };

    stage(0, 0); CP_COMMIT();
    stage(1, 1); CP_COMMIT();

    const int lrow = lane & 15;
    const int lcol = (lane >> 4) * 8;

    for (int kt = 0; kt < nk; ++kt) {
        CP_WAIT1();
        __syncthreads();

        const uint32_t aBase = smBase + (kt % 3) * (2 * STG);
        const uint32_t bBase = aBase + STG;

        #pragma unroll
        for (int ks = 0; ks < KC; ks += 16) {
            uint32_t a[4][4];
            #pragma unroll
            for (int mi = 0; mi < 4; ++mi) {
                const uint32_t ad = aBase + (uint32_t)(wm + mi * 16 + lrow) * PITCH
                                          + (uint32_t)(ks + lcol) * 2;
                ldsm_x4(a[mi][0], a[mi][1], a[mi][2], a[mi][3], ad);
            }
            uint32_t b[2][4];
            #pragma unroll
            for (int bj = 0; bj < 2; ++bj) {
                const uint32_t bd = bBase + (uint32_t)(wn + bj * 16 + lrow) * PITCH
                                          + (uint32_t)(ks + lcol) * 2;
                ldsm_x4(b[bj][0], b[bj][1], b[bj][2], b[bj][3], bd);
            }
            #pragma unroll
            for (int mi = 0; mi < 4; ++mi)
                #pragma unroll
                for (int nj = 0; nj < 4; ++nj)
                    mma16816h(acc[mi][nj], a[mi], b[nj >> 1][nj & 1], b[nj >> 1][(nj & 1) + 2]);
        }

        if (kt + 2 < nk) stage((kt + 2) % 3, kt + 2);
        CP_COMMIT();
    }

    // ---------------- epilogue ----------------
    const int r4 = lane >> 2;
    const int c2 = (lane & 3) * 2;

    float cs[4][2];
    #pragma unroll
    for (int nj = 0; nj < 4; ++nj) { cs[nj][0] = 0.f; cs[nj][1] = 0.f; }

    const int seg7 = n0 / Ec;   // EPI 7: 0=q, 1=k, 2=v (tiles never straddle)

    if (EPI == 4) __syncthreads();   // pipeline smem reuse for staging

    #pragma unroll
    for (int mi = 0; mi < 4; ++mi) {
        #pragma unroll
        for (int half = 0; half < 2; ++half) {
            const int m = m0 + wm + mi * 16 + r4 + half * 8;
            uint32_t word = 0;
            if (EPI == 4) {
                const int bq = z / Hc;
                word = mb[((size_t)bq * Sc + m) * (Sc / 32) + (size_t)(n0 + wn) / 32];
            }
            #pragma unroll
            for (int nj = 0; nj < 4; ++nj) {
                const int n = n0 + wn + nj * 8 + c2;
                float v0 = acc[mi][nj][half * 2];
                float v1 = acc[mi][nj][half * 2 + 1];
                if (EPI != 4) { v0 += bias[n]; v1 += bias[n + 1]; }
                if (EPI == 0) {
                    *reinterpret_cast<float2*>(&outF[(size_t)m * N + n]) = make_float2(v0, v1);
                } else if (EPI == 1) {
                    *reinterpret_cast<__half2*>(&outH[(size_t)m * N + n]) =
                        __floats2half2_rn(fmaxf(v0, 0.f), fmaxf(v1, 0.f));
                } else if (EPI == 4) {
                    const int bit0 = (word >> (n & 31)) & 1;
                    const int bit1 = (word >> ((n + 1) & 31)) & 1;
                    const float e0 = bit0 ? 0.f : __expf(v0 * scale);
                    const float e1 = bit1 ? 0.f : __expf(v1 * scale);
                    // stage into smem tile (row = m - m0, col = n - n0)
                    const int lr_ = wm + mi * 16 + r4 + half * 8;
                    const int lc_ = wn + nj * 8 + c2;
                    *reinterpret_cast<__half2*>(dynsm + lr_ * STGP + lc_ * 2) =
                        __floats2half2_rn(e0, e1);
                    cs[nj][0] += e0; cs[nj][1] += e1;
                } else { // EPI 7: fused QKV
                    const int col = n - seg7 * Ec;
                    const int b = m >> 11, s = m & 2047;
                    const int h = col >> 6, d = col & 63;
                    if (seg7 < 2) {
                        *reinterpret_cast<__half2*>(
                            &outH[seg7 * QKH_STRIDE +
                                  (((size_t)b * Hc + h) * Sc + s) * DHc + d]) =
                            __floats2half2_rn(v0, v1);
                    } else {
                        outF[(((size_t)b * Hc + h) * DHc + d)     * Sc + s] = v0;
                        outF[(((size_t)b * Hc + h) * DHc + d + 1) * Sc + s] = v1;
                    }
                }
            }
        }
    }

    if (EPI == 4) {
        #pragma unroll
        for (int nj = 0; nj < 4; ++nj)
            #pragma unroll
            for (int p = 0; p < 2; ++p) {
                float v = cs[nj][p];
                v += __shfl_xor_sync(0xffffffffu, v, 4);
                v += __shfl_xor_sync(0xffffffffu, v, 8);
                v += __shfl_xor_sync(0xffffffffu, v, 16);
                cs[nj][p] = v;
            }
        if (tid < 128) cs_sm[tid] = 0.f;
        __syncthreads();
        if (r4 == 0) {
            #pragma unroll
            for (int nj = 0; nj < 4; ++nj) {
                atomicAdd(&cs_sm[wn + nj * 8 + c2],     cs[nj][0]);  // 2 adds/addr: commutative
                atomicAdd(&cs_sm[wn + nj * 8 + c2 + 1], cs[nj][1]);
            }
        }
        __syncthreads();   // cs_sm ready AND all staging writes visible
        if (tid < 128)
            csP[((size_t)z * 16 + blockIdx.y) * Sc + n0 + tid] = cs_sm[tid];

        // coalesced flush: 16 threads per row, 16B each -> 256B contiguous rows
        const int chunk = tid & 15;            // 0..15 (16B units across 256B row)
        #pragma unroll
        for (int p = 0; p < 8; ++p) {
            const int r = p * 16 + (tid >> 4); // 0..127
            const uint4 v = *reinterpret_cast<const uint4*>(dynsm + r * STGP + chunk * 16);
            *reinterpret_cast<uint4*>(
                &outH[((size_t)z * Sc + m0 + r) * Sc + n0 + chunk * 8]) = v;
        }
    }
}

#define GEMM_SMEM32 (3 * 2 * 128 * 80)    // 61440 (>= 128*272 staging)
#define GEMM_SMEM64 (3 * 2 * 128 * 144)   // 110592

// ======================= attn@V: plain fp16 NT GEMM (KC=64) =================
#define AVP    144                         // bytes per smem row
#define AV_A_B (128 * AVP)                 // 18432
#define AV_B_B (64 * AVP)                  // 9216
#define AV_SMEM (3 * (AV_A_B + AV_B_B))    // 82944

__global__ void __launch_bounds__(256, 2)
gemm_av_h(const __half* __restrict__ P, const __half* __restrict__ VH,
          float* __restrict__ out)
{
    extern __shared__ char dynsm[];

    // reversed z: consume the most recently written ph slices first (L2 reuse)
    const int z = (int)gridDim.z - 1 - blockIdx.z;
    const __half* A  = P  + (size_t)z * Sc * Sc;
    const __half* Bm = VH + (size_t)z * DHc * Sc;

    const int tid  = threadIdx.x;
    const int wid  = tid >> 5;
    const int lane = tid & 31;
    const int m0   = blockIdx.y * 128;
    const int wm   = (wid & 1) * 64;
    const int wn   = (wid >> 1) * 16;

    const uint32_t smBase = smem_u32(dynsm);

    float acc[4][2][4];
    #pragma unroll
    for (int i = 0; i < 4; ++i)
        #pragma unroll
        for (int j = 0; j < 2; ++j)
            #pragma unroll
            for (int p = 0; p < 4; ++p) acc[i][j][p] = 0.f;

    const int nk = Sc / 64;   // 32

    auto stage = [&](int s, int kt) {
        const int kc = kt * 64;
        const uint32_t base = smBase + s * (AV_A_B + AV_B_B);
        #pragma unroll
        for (int i = 0; i < 6; ++i) {
            const int id = tid + i * 256;          // 0..1535
            if (id < 1024) {
                const int r = id >> 3, c = (id & 7) * 8;
                CP_ASYNC16(base + (uint32_t)(r * AVP + c * 2),
                           &A[(size_t)(m0 + r) * Sc + kc + c]);
            } else {
                const int id2 = id - 1024;
                const int r = id2 >> 3, c = (id2 & 7) * 8;
                CP_ASYNC16(base + AV_A_B + (uint32_t)(r * AVP + c * 2),
                           &Bm[(size_t)r * Sc + kc + c]);
            }
        }
    };

    stage(0, 0); CP_COMMIT();
    stage(1, 1); CP_COMMIT();

    const int lrow = lane & 15;
    const int lcol = (lane >> 4) * 8;

    for (int kt = 0; kt < nk; ++kt) {
        CP_WAIT1();
        __syncthreads();

        const uint32_t aBase = smBase + (kt % 3) * (AV_A_B + AV_B_B);
        const uint32_t bBase = aBase + AV_A_B;

        #pragma unroll
        for (int ks = 0; ks < 64; ks += 16) {
            uint32_t a[4][4];
            #pragma unroll
            for (int mi = 0; mi < 4; ++mi) {
                const uint32_t ad = aBase + (uint32_t)(wm + mi * 16 + lrow) * AVP
                                          + (uint32_t)(ks + lcol) * 2;
                ldsm_x4(a[mi][0], a[mi][1], a[mi][2], a[mi][3], ad);
            }
            uint32_t b[4];
            const uint32_t bd = bBase + (uint32_t)(wn + lrow) * AVP
                                      + (uint32_t)(ks + lcol) * 2;
            ldsm_x4(b[0], b[1], b[2], b[3], bd);
            #pragma unroll
            for (int mi = 0; mi < 4; ++mi)
                #pragma unroll
                for (int nj = 0; nj < 2; ++nj)
                    mma16816h(acc[mi][nj], a[mi], b[nj], b[nj + 2]);
        }

        if (kt + 2 < nk) stage((kt + 2) % 3, kt + 2);
        CP_COMMIT();
    }

    const int b = z / Hc, h = z % Hc;
    const int r4 = lane >> 2;
    const int c2 = (lane & 3) * 2;
    #pragma unroll
    for (int mi = 0; mi < 4; ++mi) {
        #pragma unroll
        for (int half = 0; half < 2; ++half) {
            const int s = m0 + wm + mi * 16 + r4 + half * 8;
            #pragma unroll
            for (int nj = 0; nj < 2; ++nj) {
                const int d = wn + nj * 8 + c2;
                float2 v = make_float2(acc[mi][nj][half * 2], acc[mi][nj][half * 2 + 1]);
                *reinterpret_cast<float2*>(&out[((size_t)b * Sc + s) * Dc + h * DHc + d]) = v;
            }
        }
    }
}

// ======================= small kernels ======================================
#define WQK_SZ ((size_t)Dc*Ec)            // 589824
#define W1_SZ  ((size_t)Fc*Dc)            // 2359296
#define PREP_T0 (3*WQK_SZ)                // 1769472
#define PREP_T1 (PREP_T0 + W1_SZ)         // 4128768
#define PREP_T2 (PREP_T1 + W1_SZ)         // 6488064
#define PREP_TOT (PREP_T2 + 3*Dc)         // + 2304 bias floats
#define PREP_BLOCKS ((PREP_TOT/2 + 255)/256)

__global__ void prep_kernel(const float* __restrict__ Wq, const float* __restrict__ Wk,
                            const float* __restrict__ Wv, const float* __restrict__ W1,
                            const float* __restrict__ W2,
                            const float* __restrict__ bq, const float* __restrict__ bk,
                            const float* __restrict__ bv,
                            __half* __restrict__ wqkv, __half* __restrict__ w1h,
                            __half* __restrict__ w2h, float* __restrict__ bqkv)
{
    const size_t i = ((size_t)blockIdx.x * 256 + threadIdx.x) * 2;
    if (i >= PREP_TOT) return;
    if (i < PREP_T0) {
        const float* src; size_t off;
        if (i < WQK_SZ)            { src = Wq; off = i; }
        else if (i < 2 * WQK_SZ)   { src = Wk; off = i - WQK_SZ; }
        else                       { src = Wv; off = i - 2 * WQK_SZ; }
        const float2 v = *reinterpret_cast<const float2*>(&src[off]);
        *reinterpret_cast<__half2*>(&wqkv[i]) = __floats2half2_rn(v.x, v.y);
    } else if (i < PREP_T1) {
        const size_t off = i - PREP_T0;
        const float2 v = *reinterpret_cast<const float2*>(&W1[off]);
        *reinterpret_cast<__half2*>(&w1h[off]) = __floats2half2_rn(v.x, v.y);
    } else if (i < PREP_T2) {
        const size_t off = i - PREP_T1;
        const float2 v = *reinterpret_cast<const float2*>(&W2[off]);
        *reinterpret_cast<__half2*>(&w2h[off]) = __floats2half2_rn(v.x, v.y);
    } else {
        const size_t off = i - PREP_T2;     // 0..2302, even
        const float* src; size_t o2;
        if (off < (size_t)Dc)          { src = bq; o2 = off; }
        else if (off < (size_t)2 * Dc) { src = bk; o2 = off - Dc; }
        else                           { src = bv; o2 = off - 2 * Dc; }
        const float2 v = *reinterpret_cast<const float2*>(&src[o2]);
        *reinterpret_cast<float2*>(&bqkv[off]) = v;
    }
}

__global__ void cvt_h(const float* __restrict__ src, __half* __restrict__ dst)
{
    const size_t i = ((size_t)blockIdx.x * 256 + threadIdx.x) * 2;
    const float2 v = *reinterpret_cast<const float2*>(&src[i]);
    *reinterpret_cast<__half2*>(&dst[i]) = __floats2half2_rn(v.x, v.y);
}

__global__ void maskpack_kernel(const int* __restrict__ mask, uint32_t* __restrict__ mb)
{
    const size_t w = (size_t)blockIdx.x * 256 + threadIdx.x;
    const int4* p = reinterpret_cast<const int4*>(mask + w * 32);
    uint32_t bits = 0;
    #pragma unroll
    for (int i = 0; i < 8; ++i) {
        const int4 v = p[i];
        bits |= (v.x ? 1u : 0u) << (i * 4);
        bits |= (v.y ? 1u : 0u) << (i * 4 + 1);
        bits |= (v.z ? 1u : 0u) << (i * 4 + 2);
        bits |= (v.w ? 1u : 0u) << (i * 4 + 3);
    }
    mb[w] = bits;
}

// Fused colsum + vh (bit-identical order as R15)
__global__ void vh2_kernel(const float* __restrict__ vt, const float* __restrict__ csp,
                           __half* __restrict__ vh)
{
    const size_t i = (size_t)blockIdx.x * 256 + threadIdx.x;   // z*Sc + t
    const size_t z = i >> 11;
    const int    t = (int)(i & 2047);
    float s = 0.f;
    #pragma unroll
    for (int my = 0; my < 16; ++my)
        s += csp[(z * 16 + my) * Sc + t];
    #pragma unroll 4
    for (int d = 0; d < DHc; ++d) {
        const size_t idx = ((z * DHc + d) << 11) + t;
        vh[idx] = __float2half(__fdividef(vt[idx], s));
    }
}

// LN + residual. HOUT=0: fp32 out. HOUT=1: fp16 out.
template<int HOUT>
__global__ void ln_residual_kernel(const float* __restrict__ in,
                                   const float* __restrict__ gamma,
                                   const float* __restrict__ beta,
                                   float* __restrict__ out,
                                   __half* __restrict__ outH)
{
    const size_t row = blockIdx.x;
    const float* xr = in + row * Dc;
    const int tid = threadIdx.x;

    const float v0 = xr[tid], v1 = xr[tid + 256], v2 = xr[tid + 512];

    __shared__ float red[256];
    red[tid] = v0 + v1 + v2;
    __syncthreads();
    #pragma unroll
    for (int o = 128; o > 0; o >>= 1) {
        if (tid < o) red[tid] += red[tid + o];
        __syncthreads();
    }
    const float mu = red[0] * (1.f / Dc);
    __syncthreads();

    const float d0 = v0 - mu, d1 = v1 - mu, d2 = v2 - mu;
    red[tid] = d0 * d0 + d1 * d1 + d2 * d2;
    __syncthreads();
    #pragma unroll
    for (int o = 128; o > 0; o >>= 1) {
        if (tid < o) red[tid] += red[tid + o];
        __syncthreads();
    }
    const float rstd = rsqrtf(red[0] * (1.f / Dc) + 1e-5f);

    const float o0 = d0 * rstd * gamma[tid]       + beta[tid]       + v0;
    const float o1 = d1 * rstd * gamma[tid + 256] + beta[tid + 256] + v1;
    const float o2 = d2 * rstd * gamma[tid + 512] + beta[tid + 512] + v2;

    if (HOUT == 0) {
        float* orow = out + row * Dc;
        orow[tid] = o0; orow[tid + 256] = o1; orow[tid + 512] = o2;
    } else {
        __half* orow = outH + row * Dc;
        orow[tid]       = __float2half(o0);
        orow[tid + 256] = __float2half(o1);
        orow[tid + 512] = __float2half(o2);
    }
}

// ---------------------------------------------------------------------------
extern "C" void kernel_launch(void* const* d_in, const int* in_sizes, int n_in,
                              void* d_out, int out_size)
{
    (void)in_sizes; (void)n_in; (void)out_size;
    const float* x    = (const float*)d_in[0];
    const int*   mask = (const int*)d_in[1];
    const float* Wq = (const float*)d_in[2];
    const float* bq = (const float*)d_in[3];
    const float* Wk = (const float*)d_in[4];
    const float* bk = (const float*)d_in[5];
    const float* Wv = (const float*)d_in[6];
    const float* bv = (const float*)d_in[7];
    const float* gamma = (const float*)d_in[8];
    const float* beta  = (const float*)d_in[9];
    const float* W1 = (const float*)d_in[10];
    const float* b1 = (const float*)d_in[11];
    const float* W2 = (const float*)d_in[12];
    const float* b2 = (const float*)d_in[13];
    float* out = (float*)d_out;

    float *vt, *a, *bb, *csp, *bqkv;
    __half *ph, *vh;
    uint32_t *mb;
    cudaGetSymbolAddress((void**)&vt,     g_vt);
    cudaGetSymbolAddress((void**)&a,      g_a);
    cudaGetSymbolAddress((void**)&bb,     g_b);
    cudaGetSymbolAddress((void**)&csp,    g_csp);
    cudaGetSymbolAddress((void**)&ph,     g_ph);
    cudaGetSymbolAddress((void**)&vh,     g_vh);
    cudaGetSymbolAddress((void**)&mb,     g_mb);
    cudaGetSymbolAddress((void**)&bqkv,   g_bqkv);

    __half *xh, *ah, *hh, *qkh, *wqkv, *w1h, *w2h;
    cudaGetSymbolAddress((void**)&xh,   g_xh);
    cudaGetSymbolAddress((void**)&ah,   g_ah);
    cudaGetSymbolAddress((void**)&hh,   g_hh);
    cudaGetSymbolAddress((void**)&qkh,  g_qkh);
    cudaGetSymbolAddress((void**)&wqkv, g_wqkv);
    cudaGetSymbolAddress((void**)&w1h,  g_w1h);
    cudaGetSymbolAddress((void**)&w2h,  g_w2h);

    cudaFuncSetAttribute((const void*)gemm_mma<0,64>, cudaFuncAttributeMaxDynamicSharedMemorySize, GEMM_SMEM64);
    cudaFuncSetAttribute((const void*)gemm_mma<1,64>, cudaFuncAttributeMaxDynamicSharedMemorySize, GEMM_SMEM64);
    cudaFuncSetAttribute((const void*)gemm_mma<7,64>, cudaFuncAttributeMaxDynamicSharedMemorySize, GEMM_SMEM64);
    cudaFuncSetAttribute((const void*)gemm_mma<4,32>, cudaFuncAttributeMaxDynamicSharedMemorySize, GEMM_SMEM32);
    cudaFuncSetAttribute((const void*)gemm_av_h,      cudaFuncAttributeMaxDynamicSharedMemorySize, AV_SMEM);

    const int MS = Bc * Sc;               // 8192
    const float scale = 1.0f / sqrtf((float)Sc);

    // 0) mask bit-pack + x conversion + all-weights prep
    maskpack_kernel<<<(Bc * Sc * (Sc / 32)) / 256, 256>>>(mask, mb);
    cvt_h<<<(MS * Ec) / 512, 256>>>(x, xh);
    prep_kernel<<<PREP_BLOCKS, 256>>>(Wq, Wk, Wv, W1, W2, bq, bk, bv,
                                      wqkv, w1h, w2h, bqkv);

    // 1) fused QKV projection: one GEMM, N = 2304
    {
        dim3 grid(3 * Dc / 128, MS / 128);
        gemm_mma<7,64><<<grid, 256, GEMM_SMEM64>>>(xh, wqkv, 3 * Dc, Ec, 0, 0,
                                                   bqkv, nullptr, 0.f, vt, qkh, nullptr);
    }

    // 2) p = exp(masked scores) fp16 (smem-staged store) + column partials
    {
        dim3 grid(Sc / 128, Sc / 128, Bc * Hc);
        gemm_mma<4,32><<<grid, 256, GEMM_SMEM32>>>(qkh, qkh + QKH_STRIDE, Sc, DHc,
                                                   (long)Sc * DHc, (long)Sc * DHc,
                                                   nullptr, mb, scale, nullptr, ph, csp);
    }

    // 3) fused column-sum + normalized V (fp16)
    vh2_kernel<<<(Bc * Hc * Sc) / 256, 256>>>(vt, csp, vh);

    // 4) o = p @ vh^T -> concat heads (KC=64, reversed z for L2 reuse)
    {
        dim3 grid(1, Sc / 128, Bc * Hc);
        gemm_av_h<<<grid, 256, AV_SMEM>>>(ph, vh, a);
    }

    // 5) a = LN(a) + a  -> fp16
    ln_residual_kernel<1><<<MS, 256>>>(a, gamma, beta, nullptr, ah);

    // 6) h = relu(a @ W1^T + b1) -> fp16
    {
        dim3 grid(Fc / 128, MS / 128);
        gemm_mma<1,64><<<grid, 256, GEMM_SMEM64>>>(ah, w1h, Fc, Dc, 0, 0, b1,
                                                   nullptr, 0.f, nullptr, hh, nullptr);
    }

    // 7) bb = h @ W2^T + b2
    {
        dim3 grid(Dc / 128, MS / 128);
        gemm_mma<0,64><<<grid, 256, GEMM_SMEM64>>>(hh, w2h, Dc, Fc, 0, 0, b2,
                                                   nullptr, 0.f, bb, nullptr, nullptr);
    }

    // 8) out = LN(bb) + bb
    ln_residual_kernel<0><<<MS, 256>>>(bb, gamma, beta, out, nullptr);
}

// round 17
// speedup vs baseline: 1.1878x; 1.0104x over previous
#include <cuda_runtime.h>
#include <cuda_bf16.h>
#include <cuda_fp16.h>
#include <math.h>
#include <stdint.h>

// Problem dims (fixed by the reference)
#define Bc  4
#define Sc  2048
#define Ec  768
#define Dc  768
#define Hc  12
#define DHc 64
#define Fc  3072

#define QKH_STRIDE ((size_t)Bc*Hc*Sc*DHc)

// ---------------- scratch (device globals: allocation-free) ----------------
__device__ float    g_vt[(size_t)Bc*Hc*DHc*Sc];       // [B,H,dh,S] fp32
__device__ __half   g_ph[(size_t)Bc*Hc*Sc*Sc];        // p = exp(masked score) fp16
__device__ __half   g_vh[(size_t)Bc*Hc*DHc*Sc];       // v / colsum, fp16
__device__ float    g_csp[(size_t)Bc*Hc*16*Sc];       // per-mtile column partial sums
__device__ uint32_t g_mb[(size_t)Bc*Sc*(Sc/32)];      // bit-packed mask
__device__ float    g_a [(size_t)Bc*Sc*Dc];
__device__ float    g_b [(size_t)Bc*Sc*Dc];

// fp16 operand buffers
__device__ __half g_xh  [(size_t)Bc*Sc*Ec];
__device__ __half g_ah  [(size_t)Bc*Sc*Dc];           // post-LN1 fp16
__device__ __half g_hh  [(size_t)Bc*Sc*Fc];           // hidden fp16
__device__ __half g_qkh [2*QKH_STRIDE];               // q then k
__device__ __half g_wqkv[(size_t)3*Dc*Ec];            // Wq;Wk;Wv combined
__device__ float  g_bqkv[3*Dc];                       // bq;bk;bv combined
__device__ __half g_w1h [(size_t)Fc*Dc];
__device__ __half g_w2h [(size_t)Dc*Fc];

// ======================= warp-MMA helpers ===================================
__device__ __forceinline__ uint32_t smem_u32(const void* p) {
    uint32_t a;
    asm("{ .reg .u64 t; cvta.to.shared.u64 t, %1; cvt.u32.u64 %0, t; }" : "=r"(a) : "l"(p));
    return a;
}
__device__ __forceinline__ void ldsm_x4(uint32_t& r0, uint32_t& r1, uint32_t& r2, uint32_t& r3,
                                        uint32_t addr) {
    asm volatile("ldmatrix.sync.aligned.m8n8.x4.shared.b16 {%0,%1,%2,%3}, [%4];"
                 : "=r"(r0), "=r"(r1), "=r"(r2), "=r"(r3) : "r"(addr));
}
__device__ __forceinline__ void mma16816h(float* d, const uint32_t* a, uint32_t b0, uint32_t b1) {
    asm volatile("mma.sync.aligned.m16n8k16.row.col.f32.f16.f16.f32 "
                 "{%0,%1,%2,%3}, {%4,%5,%6,%7}, {%8,%9}, {%0,%1,%2,%3};"
                 : "+f"(d[0]), "+f"(d[1]), "+f"(d[2]), "+f"(d[3])
                 : "r"(a[0]), "r"(a[1]), "r"(a[2]), "r"(a[3]), "r"(b0), "r"(b1));
}
#define CP_ASYNC16(dst, src) \
    asm volatile("cp.async.cg.shared.global [%0], [%1], 16;" :: "r"(dst), "l"(src))
#define CP_COMMIT() asm volatile("cp.async.commit_group;")
#define CP_WAIT1()  asm volatile("cp.async.wait_group 1;")

// ======================= fp16 NT GEMM via mma.sync ==========================
// C[M,N] = A[M,K] @ B[N,K]^T (fp16 operands, fp32 accumulate), batched via z.
// Tile 128x128xKC, 3-stage cp.async, 8 warps (2M x 4N), warp tile 64x32.
// EPI: 0 = +bias -> outF[m*N+n]
//      1 = relu(+bias) -> fp16 outH[m*N+n] (smem-staged, coalesced)
//      4 = scores: p = mask ? 0 : exp(acc*scale) -> fp16 outH (smem-staged);
//          col partials -> csP
//      7 = fused QKV: seg=n/768 -> 0: q scatter fp16, 1: k scatter fp16,
//          2: v scatter fp32 [b,h,d,s]; all +bias[n]
#define STGP 272   // staging pitch (bytes) for smem flush

template<int EPI, int KC>
__global__ void __launch_bounds__(256, 2)
gemm_mma(const __half* __restrict__ A, const __half* __restrict__ Bw,
         int N, int Kp, long strideA, long strideB,
         const float* __restrict__ bias, const uint32_t* __restrict__ mb, float scale,
         float* __restrict__ outF, __half* __restrict__ outH,
         float* __restrict__ csP)
{
    constexpr int PITCH = (KC == 32) ? 80 : 144;          // bytes per smem row
    constexpr int STG   = 128 * PITCH;                    // one matrix, one stage

    extern __shared__ char dynsm[];
    __shared__ float cs_sm[128];

    const int z = blockIdx.z;
    A  += (size_t)z * strideA;
    Bw += (size_t)z * strideB;

    const int tid  = threadIdx.x;
    const int wid  = tid >> 5;
    const int lane = tid & 31;
    const int m0   = blockIdx.y * 128;
    const int n0   = blockIdx.x * 128;
    const int wm   = (wid & 1) * 64;
    const int wn   = (wid >> 1) * 32;

    const uint32_t smBase = smem_u32(dynsm);

    float acc[4][4][4];
    #pragma unroll
    for (int i = 0; i < 4; ++i)
        #pragma unroll
        for (int j = 0; j < 4; ++j)
            #pragma unroll
            for (int p = 0; p < 4; ++p) acc[i][j][p] = 0.f;

    const int nk = Kp / KC;

    auto stage = [&](int s, int kt) {
        const int kc = kt * KC;
        const uint32_t base = smBase + s * (2 * STG);
        #pragma unroll
        for (int i = 0; i < KC / 16; ++i) {
            const int id = tid + i * 256;
            const int r  = id / (KC / 8);
            const int c  = (id % (KC / 8)) * 8;
            const uint32_t dA = base + (uint32_t)(r * PITCH + c * 2);
            const uint32_t dB = dA + STG;
            CP_ASYNC16(dA, &A [(size_t)(m0 + r) * Kp + kc + c]);
            CP_ASYNC16(dB, &Bw[(size_t)(n0 + r) * Kp + kc + c]);
        }
    };

    stage(0, 0); CP_COMMIT();
    stage(1, 1); CP_COMMIT();

    const int lrow = lane & 15;
    const int lcol = (lane >> 4) * 8;

    for (int kt = 0; kt < nk; ++kt) {
        CP_WAIT1();
        __syncthreads();

        const uint32_t aBase = smBase + (kt % 3) * (2 * STG);
        const uint32_t bBase = aBase + STG;

        #pragma unroll
        for (int ks = 0; ks < KC; ks += 16) {
            uint32_t a[4][4];
            #pragma unroll
            for (int mi = 0; mi < 4; ++mi) {
                const uint32_t ad = aBase + (uint32_t)(wm + mi * 16 + lrow) * PITCH
                                          + (uint32_t)(ks + lcol) * 2;
                ldsm_x4(a[mi][0], a[mi][1], a[mi][2], a[mi][3], ad);
            }
            uint32_t b[2][4];
            #pragma unroll
            for (int bj = 0; bj < 2; ++bj) {
                const uint32_t bd = bBase + (uint32_t)(wn + bj * 16 + lrow) * PITCH
                                          + (uint32_t)(ks + lcol) * 2;
                ldsm_x4(b[bj][0], b[bj][1], b[bj][2], b[bj][3], bd);
            }
            #pragma unroll
            for (int mi = 0; mi < 4; ++mi)
                #pragma unroll
                for (int nj = 0; nj < 4; ++nj)
                    mma16816h(acc[mi][nj], a[mi], b[nj >> 1][nj & 1], b[nj >> 1][(nj & 1) + 2]);
        }

        if (kt + 2 < nk) stage((kt + 2) % 3, kt + 2);
        CP_COMMIT();
    }

    // ---------------- epilogue ----------------
    const int r4 = lane >> 2;
    const int c2 = (lane & 3) * 2;

    float cs[4][2];
    #pragma unroll
    for (int nj = 0; nj < 4; ++nj) { cs[nj][0] = 0.f; cs[nj][1] = 0.f; }

    const int seg7 = n0 / Ec;   // EPI 7: 0=q, 1=k, 2=v (tiles never straddle)

    if (EPI == 4 || EPI == 1) __syncthreads();   // pipeline smem reuse for staging

    #pragma unroll
    for (int mi = 0; mi < 4; ++mi) {
        #pragma unroll
        for (int half = 0; half < 2; ++half) {
            const int m = m0 + wm + mi * 16 + r4 + half * 8;
            uint32_t word = 0;
            if (EPI == 4) {
                const int bq = z / Hc;
                word = mb[((size_t)bq * Sc + m) * (Sc / 32) + (size_t)(n0 + wn) / 32];
            }
            #pragma unroll
            for (int nj = 0; nj < 4; ++nj) {
                const int n = n0 + wn + nj * 8 + c2;
                float v0 = acc[mi][nj][half * 2];
                float v1 = acc[mi][nj][half * 2 + 1];
                if (EPI != 4) { v0 += bias[n]; v1 += bias[n + 1]; }
                if (EPI == 0) {
                    *reinterpret_cast<float2*>(&outF[(size_t)m * N + n]) = make_float2(v0, v1);
                } else if (EPI == 1) {
                    const int lr_ = wm + mi * 16 + r4 + half * 8;
                    const int lc_ = wn + nj * 8 + c2;
                    *reinterpret_cast<__half2*>(dynsm + lr_ * STGP + lc_ * 2) =
                        __floats2half2_rn(fmaxf(v0, 0.f), fmaxf(v1, 0.f));
                } else if (EPI == 4) {
                    const int bit0 = (word >> (n & 31)) & 1;
                    const int bit1 = (word >> ((n + 1) & 31)) & 1;
                    const float e0 = bit0 ? 0.f : __expf(v0 * scale);
                    const float e1 = bit1 ? 0.f : __expf(v1 * scale);
                    const int lr_ = wm + mi * 16 + r4 + half * 8;
                    const int lc_ = wn + nj * 8 + c2;
                    *reinterpret_cast<__half2*>(dynsm + lr_ * STGP + lc_ * 2) =
                        __floats2half2_rn(e0, e1);
                    cs[nj][0] += e0; cs[nj][1] += e1;
                } else { // EPI 7: fused QKV
                    const int col = n - seg7 * Ec;
                    const int b = m >> 11, s = m & 2047;
                    const int h = col >> 6, d = col & 63;
                    if (seg7 < 2) {
                        *reinterpret_cast<__half2*>(
                            &outH[seg7 * QKH_STRIDE +
                                  (((size_t)b * Hc + h) * Sc + s) * DHc + d]) =
                            __floats2half2_rn(v0, v1);
                    } else {
                        outF[(((size_t)b * Hc + h) * DHc + d)     * Sc + s] = v0;
                        outF[(((size_t)b * Hc + h) * DHc + d + 1) * Sc + s] = v1;
                    }
                }
            }
        }
    }

    if (EPI == 1) {
        __syncthreads();   // staging writes visible
        const int chunk = tid & 15;            // 16B units across 256B row
        #pragma unroll
        for (int p = 0; p < 8; ++p) {
            const int r = p * 16 + (tid >> 4);
            const uint4 v = *reinterpret_cast<const uint4*>(dynsm + r * STGP + chunk * 16);
            *reinterpret_cast<uint4*>(
                &outH[(size_t)(m0 + r) * N + n0 + chunk * 8]) = v;
        }
    }

    if (EPI == 4) {
        #pragma unroll
        for (int nj = 0; nj < 4; ++nj)
            #pragma unroll
            for (int p = 0; p < 2; ++p) {
                float v = cs[nj][p];
                v += __shfl_xor_sync(0xffffffffu, v, 4);
                v += __shfl_xor_sync(0xffffffffu, v, 8);
                v += __shfl_xor_sync(0xffffffffu, v, 16);
                cs[nj][p] = v;
            }
        if (tid < 128) cs_sm[tid] = 0.f;
        __syncthreads();
        if (r4 == 0) {
            #pragma unroll
            for (int nj = 0; nj < 4; ++nj) {
                atomicAdd(&cs_sm[wn + nj * 8 + c2],     cs[nj][0]);  // 2 adds/addr: commutative
                atomicAdd(&cs_sm[wn + nj * 8 + c2 + 1], cs[nj][1]);
            }
        }
        __syncthreads();   // cs_sm ready AND staging writes visible
        if (tid < 128)
            csP[((size_t)z * 16 + blockIdx.y) * Sc + n0 + tid] = cs_sm[tid];

        const int chunk = tid & 15;
        #pragma unroll
        for (int p = 0; p < 8; ++p) {
            const int r = p * 16 + (tid >> 4);
            const uint4 v = *reinterpret_cast<const uint4*>(dynsm + r * STGP + chunk * 16);
            *reinterpret_cast<uint4*>(
                &outH[((size_t)z * Sc + m0 + r) * Sc + n0 + chunk * 8]) = v;
        }
    }
}

#define GEMM_SMEM32 (3 * 2 * 128 * 80)    // 61440 (>= 128*272 staging)
#define GEMM_SMEM64 (3 * 2 * 128 * 144)   // 110592

// ======================= attn@V: plain fp16 NT GEMM (KC=64) =================
#define AVP    144                         // bytes per smem row
#define AV_A_B (128 * AVP)                 // 18432
#define AV_B_B (64 * AVP)                  // 9216
#define AV_SMEM (3 * (AV_A_B + AV_B_B))    // 82944

__global__ void __launch_bounds__(256, 2)
gemm_av_h(const __half* __restrict__ P, const __half* __restrict__ VH,
          float* __restrict__ out)
{
    extern __shared__ char dynsm[];

    const int z = (int)gridDim.z - 1 - blockIdx.z;   // reversed z for L2 reuse
    const __half* A  = P  + (size_t)z * Sc * Sc;
    const __half* Bm = VH + (size_t)z * DHc * Sc;

    const int tid  = threadIdx.x;
    const int wid  = tid >> 5;
    const int lane = tid & 31;
    const int m0   = blockIdx.y * 128;
    const int wm   = (wid & 1) * 64;
    const int wn   = (wid >> 1) * 16;

    const uint32_t smBase = smem_u32(dynsm);

    float acc[4][2][4];
    #pragma unroll
    for (int i = 0; i < 4; ++i)
        #pragma unroll
        for (int j = 0; j < 2; ++j)
            #pragma unroll
            for (int p = 0; p < 4; ++p) acc[i][j][p] = 0.f;

    const int nk = Sc / 64;   // 32

    auto stage = [&](int s, int kt) {
        const int kc = kt * 64;
        const uint32_t base = smBase + s * (AV_A_B + AV_B_B);
        #pragma unroll
        for (int i = 0; i < 6; ++i) {
            const int id = tid + i * 256;
            if (id < 1024) {
                const int r = id >> 3, c = (id & 7) * 8;
                CP_ASYNC16(base + (uint32_t)(r * AVP + c * 2),
                           &A[(size_t)(m0 + r) * Sc + kc + c]);
            } else {
                const int id2 = id - 1024;
                const int r = id2 >> 3, c = (id2 & 7) * 8;
                CP_ASYNC16(base + AV_A_B + (uint32_t)(r * AVP + c * 2),
                           &Bm[(size_t)r * Sc + kc + c]);
            }
        }
    };

    stage(0, 0); CP_COMMIT();
    stage(1, 1); CP_COMMIT();

    const int lrow = lane & 15;
    const int lcol = (lane >> 4) * 8;

    for (int kt = 0; kt < nk; ++kt) {
        CP_WAIT1();
        __syncthreads();

        const uint32_t aBase = smBase + (kt % 3) * (AV_A_B + AV_B_B);
        const uint32_t bBase = aBase + AV_A_B;

        #pragma unroll
        for (int ks = 0; ks < 64; ks += 16) {
            uint32_t a[4][4];
            #pragma unroll
            for (int mi = 0; mi < 4; ++mi) {
                const uint32_t ad = aBase + (uint32_t)(wm + mi * 16 + lrow) * AVP
                                          + (uint32_t)(ks + lcol) * 2;
                ldsm_x4(a[mi][0], a[mi][1], a[mi][2], a[mi][3], ad);
            }
            uint32_t b[4];
            const uint32_t bd = bBase + (uint32_t)(wn + lrow) * AVP
                                      + (uint32_t)(ks + lcol) * 2;
            ldsm_x4(b[0], b[1], b[2], b[3], bd);
            #pragma unroll
            for (int mi = 0; mi < 4; ++mi)
                #pragma unroll
                for (int nj = 0; nj < 2; ++nj)
                    mma16816h(acc[mi][nj], a[mi], b[nj], b[nj + 2]);
        }

        if (kt + 2 < nk) stage((kt + 2) % 3, kt + 2);
        CP_COMMIT();
    }

    const int b = z / Hc, h = z % Hc;
    const int r4 = lane >> 2;
    const int c2 = (lane & 3) * 2;
    #pragma unroll
    for (int mi = 0; mi < 4; ++mi) {
        #pragma unroll
        for (int half = 0; half < 2; ++half) {
            const int s = m0 + wm + mi * 16 + r4 + half * 8;
            #pragma unroll
            for (int nj = 0; nj < 2; ++nj) {
                const int d = wn + nj * 8 + c2;
                float2 v = make_float2(acc[mi][nj][half * 2], acc[mi][nj][half * 2 + 1]);
                *reinterpret_cast<float2*>(&out[((size_t)b * Sc + s) * Dc + h * DHc + d]) = v;
            }
        }
    }
}

// ======================= small kernels ======================================
#define WQK_SZ ((size_t)Dc*Ec)
#define W1_SZ  ((size_t)Fc*Dc)
#define PREP_T0 (3*WQK_SZ)
#define PREP_T1 (PREP_T0 + W1_SZ)
#define PREP_T2 (PREP_T1 + W1_SZ)
#define PREP_TOT (PREP_T2 + 3*Dc)
#define PREP_BLOCKS ((PREP_TOT/2 + 255)/256)

__global__ void prep_kernel(const float* __restrict__ Wq, const float* __restrict__ Wk,
                            const float* __restrict__ Wv, const float* __restrict__ W1,
                            const float* __restrict__ W2,
                            const float* __restrict__ bq, const float* __restrict__ bk,
                            const float* __restrict__ bv,
                            __half* __restrict__ wqkv, __half* __restrict__ w1h,
                            __half* __restrict__ w2h, float* __restrict__ bqkv)
{
    const size_t i = ((size_t)blockIdx.x * 256 + threadIdx.x) * 2;
    if (i >= PREP_TOT) return;
    if (i < PREP_T0) {
        const float* src; size_t off;
        if (i < WQK_SZ)            { src = Wq; off = i; }
        else if (i < 2 * WQK_SZ)   { src = Wk; off = i - WQK_SZ; }
        else                       { src = Wv; off = i - 2 * WQK_SZ; }
        const float2 v = *reinterpret_cast<const float2*>(&src[off]);
        *reinterpret_cast<__half2*>(&wqkv[i]) = __floats2half2_rn(v.x, v.y);
    } else if (i < PREP_T1) {
        const size_t off = i - PREP_T0;
        const float2 v = *reinterpret_cast<const float2*>(&W1[off]);
        *reinterpret_cast<__half2*>(&w1h[off]) = __floats2half2_rn(v.x, v.y);
    } else if (i < PREP_T2) {
        const size_t off = i - PREP_T1;
        const float2 v = *reinterpret_cast<const float2*>(&W2[off]);
        *reinterpret_cast<__half2*>(&w2h[off]) = __floats2half2_rn(v.x, v.y);
    } else {
        const size_t off = i - PREP_T2;
        const float* src; size_t o2;
        if (off < (size_t)Dc)          { src = bq; o2 = off; }
        else if (off < (size_t)2 * Dc) { src = bk; o2 = off - Dc; }
        else                           { src = bv; o2 = off - 2 * Dc; }
        const float2 v = *reinterpret_cast<const float2*>(&src[o2]);
        *reinterpret_cast<float2*>(&bqkv[off]) = v;
    }
}

__global__ void cvt_h(const float* __restrict__ src, __half* __restrict__ dst)
{
    const size_t i = ((size_t)blockIdx.x * 256 + threadIdx.x) * 2;
    const float2 v = *reinterpret_cast<const float2*>(&src[i]);
    *reinterpret_cast<__half2*>(&dst[i]) = __floats2half2_rn(v.x, v.y);
}

__global__ void maskpack_kernel(const int* __restrict__ mask, uint32_t* __restrict__ mb)
{
    const size_t w = (size_t)blockIdx.x * 256 + threadIdx.x;
    const int4* p = reinterpret_cast<const int4*>(mask + w * 32);
    uint32_t bits = 0;
    #pragma unroll
    for (int i = 0; i < 8; ++i) {
        const int4 v = p[i];
        bits |= (v.x ? 1u : 0u) << (i * 4);
        bits |= (v.y ? 1u : 0u) << (i * 4 + 1);
        bits |= (v.z ? 1u : 0u) << (i * 4 + 2);
        bits |= (v.w ? 1u : 0u) << (i * 4 + 3);
    }
    mb[w] = bits;
}

// Fused colsum + vh (bit-identical order)
__global__ void vh2_kernel(const float* __restrict__ vt, const float* __restrict__ csp,
                           __half* __restrict__ vh)
{
    const size_t i = (size_t)blockIdx.x * 256 + threadIdx.x;   // z*Sc + t
    const size_t z = i >> 11;
    const int    t = (int)(i & 2047);
    float s = 0.f;
    #pragma unroll
    for (int my = 0; my < 16; ++my)
        s += csp[(z * 16 + my) * Sc + t];
    #pragma unroll 4
    for (int d = 0; d < DHc; ++d) {
        const size_t idx = ((z * DHc + d) << 11) + t;
        vh[idx] = __float2half(__fdividef(vt[idx], s));
    }
}

// LN + residual. HOUT=0: fp32 out. HOUT=1: fp16 out.
template<int HOUT>
__global__ void ln_residual_kernel(const float* __restrict__ in,
                                   const float* __restrict__ gamma,
                                   const float* __restrict__ beta,
                                   float* __restrict__ out,
                                   __half* __restrict__ outH)
{
    const size_t row = blockIdx.x;
    const float* xr = in + row * Dc;
    const int tid = threadIdx.x;

    const float v0 = xr[tid], v1 = xr[tid + 256], v2 = xr[tid + 512];

    __shared__ float red[256];
    red[tid] = v0 + v1 + v2;
    __syncthreads();
    #pragma unroll
    for (int o = 128; o > 0; o >>= 1) {
        if (tid < o) red[tid] += red[tid + o];
        __syncthreads();
    }
    const float mu = red[0] * (1.f / Dc);
    __syncthreads();

    const float d0 = v0 - mu, d1 = v1 - mu, d2 = v2 - mu;
    red[tid] = d0 * d0 + d1 * d1 + d2 * d2;
    __syncthreads();
    #pragma unroll
    for (int o = 128; o > 0; o >>= 1) {
        if (tid < o) red[tid] += red[tid + o];
        __syncthreads();
    }
    const float rstd = rsqrtf(red[0] * (1.f / Dc) + 1e-5f);

    const float o0 = d0 * rstd * gamma[tid]       + beta[tid]       + v0;
    const float o1 = d1 * rstd * gamma[tid + 256] + beta[tid + 256] + v1;
    const float o2 = d2 * rstd * gamma[tid + 512] + beta[tid + 512] + v2;

    if (HOUT == 0) {
        float* orow = out + row * Dc;
        orow[tid] = o0; orow[tid + 256] = o1; orow[tid + 512] = o2;
    } else {
        __half* orow = outH + row * Dc;
        orow[tid]       = __float2half(o0);
        orow[tid + 256] = __float2half(o1);
        orow[tid + 512] = __float2half(o2);
    }
}

// ---------------------------------------------------------------------------
extern "C" void kernel_launch(void* const* d_in, const int* in_sizes, int n_in,
                              void* d_out, int out_size)
{
    (void)in_sizes; (void)n_in; (void)out_size;
    const float* x    = (const float*)d_in[0];
    const int*   mask = (const int*)d_in[1];
    const float* Wq = (const float*)d_in[2];
    const float* bq = (const float*)d_in[3];
    const float* Wk = (const float*)d_in[4];
    const float* bk = (const float*)d_in[5];
    const float* Wv = (const float*)d_in[6];
    const float* bv = (const float*)d_in[7];
    const float* gamma = (const float*)d_in[8];
    const float* beta  = (const float*)d_in[9];
    const float* W1 = (const float*)d_in[10];
    const float* b1 = (const float*)d_in[11];
    const float* W2 = (const float*)d_in[12];
    const float* b2 = (const float*)d_in[13];
    float* out = (float*)d_out;

    float *vt, *a, *bb, *csp, *bqkv;
    __half *ph, *vh;
    uint32_t *mb;
    cudaGetSymbolAddress((void**)&vt,     g_vt);
    cudaGetSymbolAddress((void**)&a,      g_a);
    cudaGetSymbolAddress((void**)&bb,     g_b);
    cudaGetSymbolAddress((void**)&csp,    g_csp);
    cudaGetSymbolAddress((void**)&ph,     g_ph);
    cudaGetSymbolAddress((void**)&vh,     g_vh);
    cudaGetSymbolAddress((void**)&mb,     g_mb);
    cudaGetSymbolAddress((void**)&bqkv,   g_bqkv);

    __half *xh, *ah, *hh, *qkh, *wqkv, *w1h, *w2h;
    cudaGetSymbolAddress((void**)&xh,   g_xh);
    cudaGetSymbolAddress((void**)&ah,   g_ah);
    cudaGetSymbolAddress((void**)&hh,   g_hh);
    cudaGetSymbolAddress((void**)&qkh,  g_qkh);
    cudaGetSymbolAddress((void**)&wqkv, g_wqkv);
    cudaGetSymbolAddress((void**)&w1h,  g_w1h);
    cudaGetSymbolAddress((void**)&w2h,  g_w2h);

    cudaFuncSetAttribute((const void*)gemm_mma<0,64>, cudaFuncAttributeMaxDynamicSharedMemorySize, GEMM_SMEM64);
    cudaFuncSetAttribute((const void*)gemm_mma<1,64>, cudaFuncAttributeMaxDynamicSharedMemorySize, GEMM_SMEM64);
    cudaFuncSetAttribute((const void*)gemm_mma<7,64>, cudaFuncAttributeMaxDynamicSharedMemorySize, GEMM_SMEM64);
    cudaFuncSetAttribute((const void*)gemm_mma<4,32>, cudaFuncAttributeMaxDynamicSharedMemorySize, GEMM_SMEM32);
    cudaFuncSetAttribute((const void*)gemm_av_h,      cudaFuncAttributeMaxDynamicSharedMemorySize, AV_SMEM);

    // side stream + events for capture-legal fork/join (created once; host-side)
    static cudaStream_t s_side = nullptr;
    static cudaEvent_t  s_evFork = nullptr, s_evJoin = nullptr;
    if (!s_side) {
        cudaStreamCreateWithFlags(&s_side, cudaStreamNonBlocking);
        cudaEventCreateWithFlags(&s_evFork, cudaEventDisableTiming);
        cudaEventCreateWithFlags(&s_evJoin, cudaEventDisableTiming);
    }
    cudaStream_t s0 = 0;   // legacy default stream (harness launches on it)

    const int MS = Bc * Sc;               // 8192
    const float scale = 1.0f / sqrtf((float)Sc);

    // 0) fork: maskpack on side stream, overlapping cvt/prep/QKV on main
    cudaEventRecord(s_evFork, s0);
    cudaStreamWaitEvent(s_side, s_evFork, 0);
    maskpack_kernel<<<(Bc * Sc * (Sc / 32)) / 256, 256, 0, s_side>>>(mask, mb);
    cudaEventRecord(s_evJoin, s_side);

    cvt_h<<<(MS * Ec) / 512, 256, 0, s0>>>(x, xh);
    prep_kernel<<<PREP_BLOCKS, 256, 0, s0>>>(Wq, Wk, Wv, W1, W2, bq, bk, bv,
                                             wqkv, w1h, w2h, bqkv);

    // 1) fused QKV projection: one GEMM, N = 2304
    {
        dim3 grid(3 * Dc / 128, MS / 128);
        gemm_mma<7,64><<<grid, 256, GEMM_SMEM64, s0>>>(xh, wqkv, 3 * Dc, Ec, 0, 0,
                                                       bqkv, nullptr, 0.f, vt, qkh, nullptr);
    }

    // join: scores needs the packed mask
    cudaStreamWaitEvent(s0, s_evJoin, 0);

    // 2) p = exp(masked scores) fp16 (smem-staged store) + column partials
    {
        dim3 grid(Sc / 128, Sc / 128, Bc * Hc);
        gemm_mma<4,32><<<grid, 256, GEMM_SMEM32, s0>>>(qkh, qkh + QKH_STRIDE, Sc, DHc,
                                                       (long)Sc * DHc, (long)Sc * DHc,
                                                       nullptr, mb, scale, nullptr, ph, csp);
    }

    // 3) fused column-sum + normalized V (fp16)
    vh2_kernel<<<(Bc * Hc * Sc) / 256, 256, 0, s0>>>(vt, csp, vh);

    // 4) o = p @ vh^T -> concat heads (KC=64, reversed z for L2 reuse)
    {
        dim3 grid(1, Sc / 128, Bc * Hc);
        gemm_av_h<<<grid, 256, AV_SMEM, s0>>>(ph, vh, a);
    }

    // 5) a = LN(a) + a  -> fp16
    ln_residual_kernel<1><<<MS, 256, 0, s0>>>(a, gamma, beta, nullptr, ah);

    // 6) h = relu(a @ W1^T + b1) -> fp16 (smem-staged store)
    {
        dim3 grid(Fc / 128, MS / 128);
        gemm_mma<1,64><<<grid, 256, GEMM_SMEM64, s0>>>(ah, w1h, Fc, Dc, 0, 0, b1,
                                                       nullptr, 0.f, nullptr, hh, nullptr);
    }

    // 7) bb = h @ W2^T + b2
    {
        dim3 grid(Dc / 128, MS / 128);
        gemm_mma<0,64><<<grid, 256, GEMM_SMEM64, s0>>>(hh, w2h, Dc, Fc, 0, 0, b2,
                                                       nullptr, 0.f, bb, nullptr, nullptr);
    }

    // 8) out = LN(bb) + bb
    ln_residual_kernel<0><<<MS, 256, 0, s0>>>(bb, gamma, beta, out, nullptr);
}